// round 1
// baseline (speedup 1.0000x reference)
#include <cuda_runtime.h>
#include <math.h>

#define TKN   8192
#define HID   1024
#define NE    8
#define TOPK  2
#define INTR  2048
#define SINT  1024

// ---------------- scratch (device globals; no allocations) ----------------
__device__ int   g_counts[NE];
__device__ int   g_offsets[NE];
__device__ int   g_cursor[NE];
__device__ int   g_tok[TKN * TOPK];          // token index per slot (grouped by expert)
__device__ float g_gate[TKN * TOPK];         // gate per slot
__device__ int   g_slot_of[TKN * TOPK];      // token -> its 2 slots
__device__ int   g_topidx[TKN * TOPK];
__device__ float g_topgate[TKN * TOPK];
__device__ float g_h[(size_t)TKN * TOPK * INTR];    // 128 MB: gelu(x @ w_fc^T), grouped
__device__ float g_partial[(size_t)TKN * TOPK * HID]; // 64 MB: gate * (h @ w_proj^T) per slot
__device__ float g_hs[(size_t)TKN * SINT];          // 32 MB: shared-expert intermediate

__device__ __forceinline__ float gelu_exact(float x) {
    return 0.5f * x * (1.0f + erff(x * 0.7071067811865476f));
}

// ---------------- init ----------------
__global__ void init_kernel() {
    int i = threadIdx.x;
    if (i < NE) g_counts[i] = 0;
}

// ---------------- router: one warp per token ----------------
__global__ void router_kernel(const float* __restrict__ x, const float* __restrict__ wg) {
    __shared__ float s_wg[NE * HID];  // 32 KB
    int tid = threadIdx.x;
    for (int i = tid; i < NE * HID; i += blockDim.x) s_wg[i] = wg[i];
    __syncthreads();

    int warp = tid >> 5, lane = tid & 31;
    int t = blockIdx.x * (blockDim.x >> 5) + warp;
    if (t >= TKN) return;

    float acc[NE];
#pragma unroll
    for (int e = 0; e < NE; e++) acc[e] = 0.0f;

    const float* xp = x + (size_t)t * HID;
    for (int k = lane; k < HID; k += 32) {
        float xv = xp[k];
#pragma unroll
        for (int e = 0; e < NE; e++) acc[e] = fmaf(xv, s_wg[e * HID + k], acc[e]);
    }
#pragma unroll
    for (int e = 0; e < NE; e++) {
#pragma unroll
        for (int o = 16; o > 0; o >>= 1) acc[e] += __shfl_xor_sync(0xffffffffu, acc[e], o);
    }
    if (lane == 0) {
        int i0 = 0; float v0 = acc[0];
#pragma unroll
        for (int e = 1; e < NE; e++) { if (acc[e] > v0) { v0 = acc[e]; i0 = e; } }
        int i1 = -1; float v1 = -1e30f;
#pragma unroll
        for (int e = 0; e < NE; e++) { if (e != i0 && acc[e] > v1) { v1 = acc[e]; i1 = e; } }
        // softmax over the two selected logits (v0 >= v1)
        float e1 = expf(v1 - v0);
        float denom = 1.0f + e1;
        float gate0 = 1.0f / denom;
        float gate1 = e1 / denom;
        g_topidx[t * 2 + 0] = i0;  g_topgate[t * 2 + 0] = gate0;
        g_topidx[t * 2 + 1] = i1;  g_topgate[t * 2 + 1] = gate1;
        atomicAdd(&g_counts[i0], 1);
        atomicAdd(&g_counts[i1], 1);
    }
}

// ---------------- prefix (tiny) ----------------
__global__ void prefix_kernel() {
    if (threadIdx.x == 0) {
        int s = 0;
        for (int e = 0; e < NE; e++) { g_offsets[e] = s; s += g_counts[e]; g_cursor[e] = 0; }
    }
}

// ---------------- scatter tokens into per-expert contiguous lists ----------------
__global__ void scatter_kernel() {
    int t = blockIdx.x * blockDim.x + threadIdx.x;
    if (t >= TKN) return;
#pragma unroll
    for (int k = 0; k < TOPK; k++) {
        int e = g_topidx[t * 2 + k];
        int slot = atomicAdd(&g_cursor[e], 1);
        int pos = g_offsets[e] + slot;
        g_tok[pos] = t;
        g_gate[pos] = g_topgate[t * 2 + k];
        g_slot_of[t * 2 + k] = pos;
    }
}

// ---------------- tiled SGEMM (NT: both operands K-contiguous) ----------------
// MODE 0: expert fc   : A = x (gathered rows),   B = w_fc[e],   C = g_h (gelu)
// MODE 1: expert proj : A = g_h (grouped),       B = w_proj[e], C = g_partial (gate scale)
// MODE 2: shared fc   : A = x,                   B = w_fc_s,    C = g_hs (gelu)
// MODE 3: shared proj : A = g_hs,                B = w_proj_s,  C = out (plain)
template <int MODE>
__global__ void __launch_bounds__(256) gemm_kernel(
    const float* __restrict__ Ain, const float* __restrict__ Bin,
    float* __restrict__ Cout, int Kdim, int Ndim)
{
    constexpr int BM = 128, BN = 128, BK = 16;

    int rows, base;
    const float* Bp;
    if (MODE <= 1) {
        int e = blockIdx.z;
        rows = g_counts[e];
        base = g_offsets[e];
        Bp = Bin + (size_t)e * Kdim * Ndim;
    } else {
        rows = TKN; base = 0; Bp = Bin;
    }
    int bm = blockIdx.y;
    if (bm * BM >= rows) return;
    int bn = blockIdx.x;

    __shared__ float As[BK][BM + 4];
    __shared__ float Bs[BK][BN + 4];

    int tid = threadIdx.x;
    int tx = tid & 15, ty = tid >> 4;

    float acc[8][8];
#pragma unroll
    for (int i = 0; i < 8; i++)
#pragma unroll
        for (int j = 0; j < 8; j++) acc[i][j] = 0.0f;

    for (int k0 = 0; k0 < Kdim; k0 += BK) {
        // load A tile (transposed into As[k][m])
#pragma unroll
        for (int l = 0; l < 2; l++) {
            int f  = tid + l * 256;
            int m  = f >> 2;
            int kq = (f & 3) << 2;
            int gm = bm * BM + m;
            float4 v = make_float4(0.f, 0.f, 0.f, 0.f);
            if (gm < rows) {
                const float* ap;
                if (MODE == 0)      ap = Ain + (size_t)g_tok[base + gm] * Kdim;
                else if (MODE == 1) ap = g_h + (size_t)(base + gm) * Kdim;
                else if (MODE == 2) ap = Ain + (size_t)gm * Kdim;
                else                ap = g_hs + (size_t)gm * Kdim;
                v = *reinterpret_cast<const float4*>(ap + k0 + kq);
            }
            As[kq + 0][m] = v.x; As[kq + 1][m] = v.y; As[kq + 2][m] = v.z; As[kq + 3][m] = v.w;
        }
        // load B tile (Bs[k][n])
#pragma unroll
        for (int l = 0; l < 2; l++) {
            int f  = tid + l * 256;
            int n  = f >> 2;
            int kq = (f & 3) << 2;
            int gn = bn * BN + n;
            float4 v = *reinterpret_cast<const float4*>(Bp + (size_t)gn * Kdim + k0 + kq);
            Bs[kq + 0][n] = v.x; Bs[kq + 1][n] = v.y; Bs[kq + 2][n] = v.z; Bs[kq + 3][n] = v.w;
        }
        __syncthreads();

#pragma unroll
        for (int kk = 0; kk < BK; kk++) {
            float a[8], b[8];
            *reinterpret_cast<float4*>(&a[0]) = *reinterpret_cast<const float4*>(&As[kk][ty * 8 + 0]);
            *reinterpret_cast<float4*>(&a[4]) = *reinterpret_cast<const float4*>(&As[kk][ty * 8 + 4]);
            *reinterpret_cast<float4*>(&b[0]) = *reinterpret_cast<const float4*>(&Bs[kk][tx * 8 + 0]);
            *reinterpret_cast<float4*>(&b[4]) = *reinterpret_cast<const float4*>(&Bs[kk][tx * 8 + 4]);
#pragma unroll
            for (int i = 0; i < 8; i++)
#pragma unroll
                for (int j = 0; j < 8; j++)
                    acc[i][j] = fmaf(a[i], b[j], acc[i][j]);
        }
        __syncthreads();
    }

    // epilogue
#pragma unroll
    for (int i = 0; i < 8; i++) {
        int gm = bm * BM + ty * 8 + i;
        if (gm >= rows) continue;
        float* cp;
        float scale = 1.0f;
        if (MODE == 0)      cp = g_h + (size_t)(base + gm) * Ndim;
        else if (MODE == 1) { cp = g_partial + (size_t)(base + gm) * Ndim; scale = g_gate[base + gm]; }
        else if (MODE == 2) cp = g_hs + (size_t)gm * Ndim;
        else                cp = Cout + (size_t)gm * Ndim;
        int gn0 = bn * BN + tx * 8;
#pragma unroll
        for (int j = 0; j < 8; j += 4) {
            float4 v;
            if (MODE == 0 || MODE == 2) {
                v.x = gelu_exact(acc[i][j + 0]);
                v.y = gelu_exact(acc[i][j + 1]);
                v.z = gelu_exact(acc[i][j + 2]);
                v.w = gelu_exact(acc[i][j + 3]);
            } else {
                v.x = scale * acc[i][j + 0];
                v.y = scale * acc[i][j + 1];
                v.z = scale * acc[i][j + 2];
                v.w = scale * acc[i][j + 3];
            }
            *reinterpret_cast<float4*>(cp + gn0 + j) = v;
        }
    }
}

// ---------------- combine: out += partial[slot0] + partial[slot1] ----------------
__global__ void combine_kernel(float* __restrict__ out) {
    constexpr int NV = HID / 4;
    int idx = blockIdx.x * blockDim.x + threadIdx.x;
    if (idx >= TKN * NV) return;
    int t = idx / NV, n4 = idx % NV;
    int s0 = g_slot_of[t * 2 + 0];
    int s1 = g_slot_of[t * 2 + 1];
    float4 o = reinterpret_cast<float4*>(out)[idx];
    const float4* P = reinterpret_cast<const float4*>(g_partial);
    float4 p0 = P[(size_t)s0 * NV + n4];
    float4 p1 = P[(size_t)s1 * NV + n4];
    o.x += p0.x + p1.x;
    o.y += p0.y + p1.y;
    o.z += p0.z + p1.z;
    o.w += p0.w + p1.w;
    reinterpret_cast<float4*>(out)[idx] = o;
}

// ---------------- launch ----------------
extern "C" void kernel_launch(void* const* d_in, const int* in_sizes, int n_in,
                              void* d_out, int out_size) {
    (void)in_sizes; (void)n_in; (void)out_size;
    const float* x      = (const float*)d_in[0];
    const float* wg     = (const float*)d_in[1];
    const float* wfc    = (const float*)d_in[2];
    const float* wproj  = (const float*)d_in[3];
    const float* wfcs   = (const float*)d_in[4];
    const float* wprojs = (const float*)d_in[5];
    float* out = (float*)d_out;

    init_kernel<<<1, 32>>>();
    router_kernel<<<TKN / 8, 256>>>(x, wg);
    prefix_kernel<<<1, 32>>>();
    scatter_kernel<<<TKN / 256, 256>>>();

    // expert fc: [rows_e,1024] @ [2048,1024]^T -> gelu -> g_h
    gemm_kernel<0><<<dim3(INTR / 128, TKN / 128, NE), 256>>>(x, wfc, nullptr, HID, INTR);
    // shared fc: [8192,1024] @ [1024,1024]^T -> gelu -> g_hs
    gemm_kernel<2><<<dim3(SINT / 128, TKN / 128, 1), 256>>>(x, wfcs, nullptr, HID, SINT);
    // expert proj: [rows_e,2048] @ [1024,2048]^T -> gate-scaled -> g_partial
    gemm_kernel<1><<<dim3(HID / 128, TKN / 128, NE), 256>>>(nullptr, wproj, nullptr, INTR, HID);
    // shared proj: [8192,1024] @ [1024,1024]^T -> out
    gemm_kernel<3><<<dim3(HID / 128, TKN / 128, 1), 256>>>(nullptr, wprojs, out, SINT, HID);

    combine_kernel<<<(TKN * (HID / 4)) / 256, 256>>>(out);
}

// round 3
// speedup vs baseline: 2.1319x; 2.1319x over previous
#include <cuda_runtime.h>
#include <cuda_bf16.h>
#include <math.h>
#include <stdint.h>

#define TKN   8192
#define HID   1024
#define NE    8
#define TOPK  2
#define INTR  2048
#define SINT  1024

// ===================== scratch (device globals; no allocations) =====================
__device__ int   g_counts[NE];
__device__ int   g_offsets[NE];
__device__ int   g_cursor[NE];
__device__ __align__(16) int   g_tok[TKN * TOPK];
__device__ __align__(16) float g_gate[TKN * TOPK];
__device__ __align__(16) int   g_slot_of[TKN * TOPK];
__device__ __align__(16) int   g_topidx[TKN * TOPK];
__device__ __align__(16) float g_topgate[TKN * TOPK];

__device__ __align__(16) __nv_bfloat16 g_x_hi[(size_t)TKN * HID];
__device__ __align__(16) __nv_bfloat16 g_x_lo[(size_t)TKN * HID];
__device__ __align__(16) __nv_bfloat16 g_wfc_hi[(size_t)NE * INTR * HID];
__device__ __align__(16) __nv_bfloat16 g_wfc_lo[(size_t)NE * INTR * HID];
__device__ __align__(16) __nv_bfloat16 g_wpj_hi[(size_t)NE * HID * INTR];
__device__ __align__(16) __nv_bfloat16 g_wpj_lo[(size_t)NE * HID * INTR];
__device__ __align__(16) __nv_bfloat16 g_wfcs_hi[(size_t)SINT * HID];
__device__ __align__(16) __nv_bfloat16 g_wfcs_lo[(size_t)SINT * HID];
__device__ __align__(16) __nv_bfloat16 g_wpjs_hi[(size_t)HID * SINT];
__device__ __align__(16) __nv_bfloat16 g_wpjs_lo[(size_t)HID * SINT];
__device__ __align__(16) __nv_bfloat16 g_h_hi[(size_t)TKN * TOPK * INTR];
__device__ __align__(16) __nv_bfloat16 g_h_lo[(size_t)TKN * TOPK * INTR];
__device__ __align__(16) __nv_bfloat16 g_hs_hi[(size_t)TKN * SINT];
__device__ __align__(16) __nv_bfloat16 g_hs_lo[(size_t)TKN * SINT];
__device__ __align__(16) float g_partial[(size_t)TKN * TOPK * HID];

__device__ __forceinline__ float gelu_exact(float x) {
    return 0.5f * x * (1.0f + erff(x * 0.7071067811865476f));
}

// ===================== PTX helpers (base-target only: sm_80-class) =====================
__device__ __forceinline__ uint32_t smem_to_u32(const void* p) {
    uint32_t a;
    asm("{ .reg .u64 t; cvta.to.shared.u64 t, %1; cvt.u32.u64 %0, t; }" : "=r"(a) : "l"(p));
    return a;
}
__device__ __forceinline__ void cp_async16(uint32_t dst, const void* src, uint32_t sz) {
    asm volatile(
        "{ .reg .u64 g; cvta.to.global.u64 g, %1;\n\t"
        "cp.async.cg.shared.global [%0], [g], 16, %2; }"
        :: "r"(dst), "l"(src), "r"(sz));
}
#define CP_COMMIT() asm volatile("cp.async.commit_group;" ::: "memory")
#define CP_WAIT(n)  asm volatile("cp.async.wait_group %0;" :: "n"(n) : "memory")

__device__ __forceinline__ void ldsm4(uint32_t& r0, uint32_t& r1, uint32_t& r2, uint32_t& r3,
                                      uint32_t addr) {
    asm volatile("ldmatrix.sync.aligned.m8n8.x4.shared.b16 {%0,%1,%2,%3}, [%4];"
        : "=r"(r0), "=r"(r1), "=r"(r2), "=r"(r3) : "r"(addr));
}
__device__ __forceinline__ void mma16816(float* c, const uint32_t* a, const uint32_t* b) {
    asm volatile(
        "mma.sync.aligned.m16n8k16.row.col.f32.bf16.bf16.f32 "
        "{%0,%1,%2,%3}, {%4,%5,%6,%7}, {%8,%9}, {%0,%1,%2,%3};"
        : "+f"(c[0]), "+f"(c[1]), "+f"(c[2]), "+f"(c[3])
        : "r"(a[0]), "r"(a[1]), "r"(a[2]), "r"(a[3]), "r"(b[0]), "r"(b[1]));
}

// ===================== small kernels =====================
__global__ void init_kernel() {
    int i = threadIdx.x;
    if (i < NE) g_counts[i] = 0;
}

__global__ void router_kernel(const float* __restrict__ x, const float* __restrict__ wg) {
    __shared__ float s_wg[NE * HID];
    int tid = threadIdx.x;
    for (int i = tid; i < NE * HID; i += blockDim.x) s_wg[i] = wg[i];
    __syncthreads();
    int warp = tid >> 5, lane = tid & 31;
    int t = blockIdx.x * (blockDim.x >> 5) + warp;
    if (t >= TKN) return;
    float acc[NE];
#pragma unroll
    for (int e = 0; e < NE; e++) acc[e] = 0.0f;
    const float* xp = x + (size_t)t * HID;
    for (int k = lane; k < HID; k += 32) {
        float xv = xp[k];
#pragma unroll
        for (int e = 0; e < NE; e++) acc[e] = fmaf(xv, s_wg[e * HID + k], acc[e]);
    }
#pragma unroll
    for (int e = 0; e < NE; e++) {
#pragma unroll
        for (int o = 16; o > 0; o >>= 1) acc[e] += __shfl_xor_sync(0xffffffffu, acc[e], o);
    }
    if (lane == 0) {
        int i0 = 0; float v0 = acc[0];
#pragma unroll
        for (int e = 1; e < NE; e++) { if (acc[e] > v0) { v0 = acc[e]; i0 = e; } }
        int i1 = -1; float v1 = -1e30f;
#pragma unroll
        for (int e = 0; e < NE; e++) { if (e != i0 && acc[e] > v1) { v1 = acc[e]; i1 = e; } }
        float e1 = expf(v1 - v0);
        float denom = 1.0f + e1;
        g_topidx[t * 2 + 0] = i0;  g_topgate[t * 2 + 0] = 1.0f / denom;
        g_topidx[t * 2 + 1] = i1;  g_topgate[t * 2 + 1] = e1 / denom;
        atomicAdd(&g_counts[i0], 1);
        atomicAdd(&g_counts[i1], 1);
    }
}

__global__ void prefix_kernel() {
    if (threadIdx.x == 0) {
        int s = 0;
        for (int e = 0; e < NE; e++) { g_offsets[e] = s; s += g_counts[e]; g_cursor[e] = 0; }
    }
}

__global__ void scatter_kernel() {
    int t = blockIdx.x * blockDim.x + threadIdx.x;
    if (t >= TKN) return;
#pragma unroll
    for (int k = 0; k < TOPK; k++) {
        int e = g_topidx[t * 2 + k];
        int slot = atomicAdd(&g_cursor[e], 1);
        int pos = g_offsets[e] + slot;
        g_tok[pos] = t;
        g_gate[pos] = g_topgate[t * 2 + k];
        g_slot_of[t * 2 + k] = pos;
    }
}

// fp32 -> bf16 (hi) + bf16 residual (lo)
__global__ void split_kernel(const float* __restrict__ src,
                             __nv_bfloat16* __restrict__ hi,
                             __nv_bfloat16* __restrict__ lo, int n) {
    int i = (blockIdx.x * blockDim.x + threadIdx.x) * 4;
    if (i >= n) return;
    float4 v = *reinterpret_cast<const float4*>(src + i);
    __nv_bfloat16 h0 = __float2bfloat16(v.x), h1 = __float2bfloat16(v.y);
    __nv_bfloat16 h2 = __float2bfloat16(v.z), h3 = __float2bfloat16(v.w);
    __nv_bfloat16 l0 = __float2bfloat16(v.x - __bfloat162float(h0));
    __nv_bfloat16 l1 = __float2bfloat16(v.y - __bfloat162float(h1));
    __nv_bfloat16 l2 = __float2bfloat16(v.z - __bfloat162float(h2));
    __nv_bfloat16 l3 = __float2bfloat16(v.w - __bfloat162float(h3));
    uint2 hp, lp;
    hp.x = (uint32_t)__bfloat16_as_ushort(h0) | ((uint32_t)__bfloat16_as_ushort(h1) << 16);
    hp.y = (uint32_t)__bfloat16_as_ushort(h2) | ((uint32_t)__bfloat16_as_ushort(h3) << 16);
    lp.x = (uint32_t)__bfloat16_as_ushort(l0) | ((uint32_t)__bfloat16_as_ushort(l1) << 16);
    lp.y = (uint32_t)__bfloat16_as_ushort(l2) | ((uint32_t)__bfloat16_as_ushort(l3) << 16);
    *reinterpret_cast<uint2*>(hi + i) = hp;
    *reinterpret_cast<uint2*>(lo + i) = lp;
}

// ===================== mma.sync grouped GEMM =====================
// Block tile 128x128, BK=32 bf16. 8 warps (2 x 4), warp tile 64x32.
// 3-pass fp32 emulation: acc += Ahi*Bhi + Ahi*Blo + Alo*Bhi.
// Smem per stage: 4 tiles of 128 rows x 40 bf16 (80B padded rows) = 40960 B. 2 stages.
#define TILE_B   10240
#define STAGE_B  40960
#define SMEM_MMA (2 * STAGE_B)

template <int MODE>
__global__ void __launch_bounds__(256, 1) mma_gemm(float* __restrict__ outp)
{
    constexpr int KD = (MODE == 1) ? INTR : HID;
    constexpr int ND = (MODE == 0) ? INTR : ((MODE == 2) ? SINT : HID);
    constexpr int ITERS = KD / 32;

    int rows, base, e = 0;
    if (MODE <= 1) {
        e = blockIdx.z;
        rows = g_counts[e];
        base = g_offsets[e];
    } else { rows = TKN; base = 0; }
    const int bm = blockIdx.y;
    if (bm * 128 >= rows) return;
    const int bn = blockIdx.x;

    extern __shared__ char smem[];
    const uint32_t sb = smem_to_u32(smem);

    const int tid = threadIdx.x;
    const int wid = tid >> 5, lid = tid & 31;
    const int warp_m = wid & 1;      // 0..1 -> 64-row halves
    const int warp_n = wid >> 1;     // 0..3 -> 32-col quarters

    const __nv_bfloat16 *Ahi, *Alo, *Bhi, *Blo;
    if (MODE == 0)      { Ahi = g_x_hi;  Alo = g_x_lo; }
    else if (MODE == 1) { Ahi = g_h_hi;  Alo = g_h_lo; }
    else if (MODE == 2) { Ahi = g_x_hi;  Alo = g_x_lo; }
    else                { Ahi = g_hs_hi; Alo = g_hs_lo; }
    if (MODE == 0)      { Bhi = g_wfc_hi  + (size_t)e * INTR * HID; Blo = g_wfc_lo  + (size_t)e * INTR * HID; }
    else if (MODE == 1) { Bhi = g_wpj_hi  + (size_t)e * HID * INTR; Blo = g_wpj_lo  + (size_t)e * HID * INTR; }
    else if (MODE == 2) { Bhi = g_wfcs_hi; Blo = g_wfcs_lo; }
    else                { Bhi = g_wpjs_hi; Blo = g_wpjs_lo; }

    float acc[4][4][4];
#pragma unroll
    for (int i = 0; i < 4; i++)
#pragma unroll
        for (int j = 0; j < 4; j++)
#pragma unroll
            for (int q = 0; q < 4; q++) acc[i][j][q] = 0.0f;

    // -------- stage loader --------
    auto load_stage = [&](int it, int s) {
        const int k0 = it * 32;
        const uint32_t stBase = sb + (uint32_t)s * STAGE_B;
#pragma unroll
        for (int l = 0; l < 2; l++) {
            int u = tid + l * 256;
            int r = u >> 2, ch = u & 3;
            uint32_t so = stBase + r * 80 + ch * 16;
            // A (hi + lo)
            int gm = bm * 128 + r;
            uint32_t szA = 16;
            size_t srow;
            if (MODE == 0) {
                if (gm < rows) srow = (size_t)g_tok[base + gm];
                else { srow = 0; szA = 0; }
            } else if (MODE == 1) {
                if (gm < rows) srow = (size_t)(base + gm);
                else { srow = (size_t)base; szA = 0; }
            } else srow = (size_t)gm;
            size_t goff = srow * KD + k0 + ch * 8;
            cp_async16(so,              Ahi + goff, szA);
            cp_async16(so + TILE_B,     Alo + goff, szA);
            // B (hi + lo)
            size_t boff = (size_t)(bn * 128 + r) * KD + k0 + ch * 8;
            cp_async16(so + 2 * TILE_B, Bhi + boff, 16);
            cp_async16(so + 3 * TILE_B, Blo + boff, 16);
        }
    };

    // -------- compute one stage --------
    auto compute_stage = [&](int s) {
        const uint32_t aB = sb + (uint32_t)s * STAGE_B;
        const uint32_t bB = aB + 2 * TILE_B;
#pragma unroll
        for (int h = 0; h < 2; h++) {
            uint32_t ahi[4][4], alo[4][4], bhi[4][2], blo[4][2];
#pragma unroll
            for (int i = 0; i < 4; i++) {
                int row = warp_m * 64 + i * 16 + (lid & 7) + ((lid >> 3) & 1) * 8;
                int ch  = h * 2 + (lid >> 4);
                uint32_t ad = aB + row * 80 + ch * 16;
                ldsm4(ahi[i][0], ahi[i][1], ahi[i][2], ahi[i][3], ad);
                ldsm4(alo[i][0], alo[i][1], alo[i][2], alo[i][3], ad + TILE_B);
            }
#pragma unroll
            for (int jj = 0; jj < 2; jj++) {
                int nrow = warp_n * 32 + jj * 16 + ((lid >> 4) & 1) * 8 + (lid & 7);
                int ch   = h * 2 + ((lid >> 3) & 1);
                uint32_t bd = bB + nrow * 80 + ch * 16;
                uint32_t r0, r1, r2, r3;
                ldsm4(r0, r1, r2, r3, bd);
                bhi[2 * jj][0] = r0; bhi[2 * jj][1] = r1;
                bhi[2 * jj + 1][0] = r2; bhi[2 * jj + 1][1] = r3;
                ldsm4(r0, r1, r2, r3, bd + TILE_B);
                blo[2 * jj][0] = r0; blo[2 * jj][1] = r1;
                blo[2 * jj + 1][0] = r2; blo[2 * jj + 1][1] = r3;
            }
#pragma unroll
            for (int i = 0; i < 4; i++)
#pragma unroll
                for (int j = 0; j < 4; j++) {
                    mma16816(acc[i][j], ahi[i], bhi[j]);
                    mma16816(acc[i][j], ahi[i], blo[j]);
                    mma16816(acc[i][j], alo[i], bhi[j]);
                }
        }
    };

    // -------- pipeline --------
    load_stage(0, 0); CP_COMMIT();
    load_stage(1, 1); CP_COMMIT();
#pragma unroll 1
    for (int it = 0; it < ITERS; ++it) {
        if (it + 1 < ITERS) { CP_WAIT(1); } else { CP_WAIT(0); }
        __syncthreads();
        compute_stage(it & 1);
        __syncthreads();
        if (it + 2 < ITERS) { load_stage(it + 2, it & 1); CP_COMMIT(); }
    }

    // -------- epilogue --------
    const int g = lid >> 2, t4 = lid & 3;
#pragma unroll
    for (int i = 0; i < 4; i++) {
#pragma unroll
        for (int half = 0; half < 2; half++) {
            int row = bm * 128 + warp_m * 64 + i * 16 + g + half * 8;
            if (row >= rows) continue;
            float gate = 1.0f;
            if (MODE == 1) gate = g_gate[base + row];
#pragma unroll
            for (int j = 0; j < 4; j++) {
                float c0 = acc[i][j][half * 2 + 0];
                float c1 = acc[i][j][half * 2 + 1];
                int col = bn * 128 + warp_n * 32 + j * 8 + t4 * 2;
                if (MODE == 0 || MODE == 2) {
                    float f0 = gelu_exact(c0), f1 = gelu_exact(c1);
                    __nv_bfloat16 h0 = __float2bfloat16(f0);
                    __nv_bfloat16 h1 = __float2bfloat16(f1);
                    __nv_bfloat16 l0 = __float2bfloat16(f0 - __bfloat162float(h0));
                    __nv_bfloat16 l1 = __float2bfloat16(f1 - __bfloat162float(h1));
                    uint32_t hp = (uint32_t)__bfloat16_as_ushort(h0) | ((uint32_t)__bfloat16_as_ushort(h1) << 16);
                    uint32_t lp = (uint32_t)__bfloat16_as_ushort(l0) | ((uint32_t)__bfloat16_as_ushort(l1) << 16);
                    __nv_bfloat16* Hh = (MODE == 0) ? g_h_hi : g_hs_hi;
                    __nv_bfloat16* Hl = (MODE == 0) ? g_h_lo : g_hs_lo;
                    size_t off = (MODE == 0) ? ((size_t)(base + row) * ND + col)
                                             : ((size_t)row * ND + col);
                    *reinterpret_cast<uint32_t*>(Hh + off) = hp;
                    *reinterpret_cast<uint32_t*>(Hl + off) = lp;
                } else if (MODE == 1) {
                    size_t off = (size_t)(base + row) * HID + col;
                    float2 v = make_float2(gate * c0, gate * c1);
                    *reinterpret_cast<float2*>(g_partial + off) = v;
                } else {
                    size_t off = (size_t)row * HID + col;
                    float2 v = make_float2(c0, c1);
                    *reinterpret_cast<float2*>(outp + off) = v;
                }
            }
        }
    }
}

// ---------------- combine ----------------
__global__ void combine_kernel(float* __restrict__ out) {
    constexpr int NV = HID / 4;
    int idx = blockIdx.x * blockDim.x + threadIdx.x;
    if (idx >= TKN * NV) return;
    int t = idx / NV, n4 = idx % NV;
    int s0 = g_slot_of[t * 2 + 0];
    int s1 = g_slot_of[t * 2 + 1];
    float4 o = reinterpret_cast<float4*>(out)[idx];
    const float4* P = reinterpret_cast<const float4*>(g_partial);
    float4 p0 = P[(size_t)s0 * NV + n4];
    float4 p1 = P[(size_t)s1 * NV + n4];
    o.x += p0.x + p1.x;
    o.y += p0.y + p1.y;
    o.z += p0.z + p1.z;
    o.w += p0.w + p1.w;
    reinterpret_cast<float4*>(out)[idx] = o;
}

// ===================== launch =====================
extern "C" void kernel_launch(void* const* d_in, const int* in_sizes, int n_in,
                              void* d_out, int out_size) {
    (void)in_sizes; (void)n_in; (void)out_size;
    const float* x      = (const float*)d_in[0];
    const float* wg     = (const float*)d_in[1];
    const float* wfc    = (const float*)d_in[2];
    const float* wproj  = (const float*)d_in[3];
    const float* wfcs   = (const float*)d_in[4];
    const float* wprojs = (const float*)d_in[5];
    float* out = (float*)d_out;

    static bool attr_set = false;
    if (!attr_set) {
        cudaFuncSetAttribute(mma_gemm<0>, cudaFuncAttributeMaxDynamicSharedMemorySize, SMEM_MMA);
        cudaFuncSetAttribute(mma_gemm<1>, cudaFuncAttributeMaxDynamicSharedMemorySize, SMEM_MMA);
        cudaFuncSetAttribute(mma_gemm<2>, cudaFuncAttributeMaxDynamicSharedMemorySize, SMEM_MMA);
        cudaFuncSetAttribute(mma_gemm<3>, cudaFuncAttributeMaxDynamicSharedMemorySize, SMEM_MMA);
        attr_set = true;
    }

    init_kernel<<<1, 32>>>();
    router_kernel<<<TKN / 8, 256>>>(x, wg);
    prefix_kernel<<<1, 32>>>();
    scatter_kernel<<<TKN / 256, 256>>>();

    {
        __nv_bfloat16 *hi, *lo;
        cudaGetSymbolAddress((void**)&hi, g_x_hi);  cudaGetSymbolAddress((void**)&lo, g_x_lo);
        split_kernel<<<(TKN * HID) / 1024, 256>>>(x, hi, lo, TKN * HID);
        cudaGetSymbolAddress((void**)&hi, g_wfc_hi); cudaGetSymbolAddress((void**)&lo, g_wfc_lo);
        split_kernel<<<(NE * INTR * HID) / 1024, 256>>>(wfc, hi, lo, NE * INTR * HID);
        cudaGetSymbolAddress((void**)&hi, g_wpj_hi); cudaGetSymbolAddress((void**)&lo, g_wpj_lo);
        split_kernel<<<(NE * HID * INTR) / 1024, 256>>>(wproj, hi, lo, NE * HID * INTR);
        cudaGetSymbolAddress((void**)&hi, g_wfcs_hi); cudaGetSymbolAddress((void**)&lo, g_wfcs_lo);
        split_kernel<<<(SINT * HID) / 1024, 256>>>(wfcs, hi, lo, SINT * HID);
        cudaGetSymbolAddress((void**)&hi, g_wpjs_hi); cudaGetSymbolAddress((void**)&lo, g_wpjs_lo);
        split_kernel<<<(HID * SINT) / 1024, 256>>>(wprojs, hi, lo, HID * SINT);
    }

    // expert fc: gathered x -> gelu -> g_h (bf16 hi/lo)
    mma_gemm<0><<<dim3(INTR / 128, TKN * TOPK / 128, NE), 256, SMEM_MMA>>>(nullptr);
    // shared fc: x -> gelu -> g_hs
    mma_gemm<2><<<dim3(SINT / 128, TKN / 128, 1), 256, SMEM_MMA>>>(nullptr);
    // expert proj: g_h -> gate-scaled -> g_partial
    mma_gemm<1><<<dim3(HID / 128, TKN * TOPK / 128, NE), 256, SMEM_MMA>>>(nullptr);
    // shared proj: g_hs -> out
    mma_gemm<3><<<dim3(HID / 128, TKN / 128, 1), 256, SMEM_MMA>>>(out);

    combine_kernel<<<(TKN * (HID / 4)) / 256, 256>>>(out);
}

// round 4
// speedup vs baseline: 2.4807x; 1.1636x over previous
#include <cuda_runtime.h>
#include <cuda_bf16.h>
#include <math.h>
#include <stdint.h>

#define TKN   8192
#define HID   1024
#define NE    8
#define TOPK  2
#define INTR  2048
#define SINT  1024

// ===================== scratch (device globals; no allocations) =====================
__device__ int   g_counts[NE];
__device__ int   g_offsets[NE];
__device__ int   g_cursor[NE];
__device__ __align__(16) int   g_tok[TKN * TOPK];
__device__ __align__(16) float g_gate[TKN * TOPK];
__device__ __align__(16) int   g_slot_of[TKN * TOPK];
__device__ __align__(16) int   g_topidx[TKN * TOPK];
__device__ __align__(16) float g_topgate[TKN * TOPK];

__device__ __align__(16) __nv_bfloat16 g_x_hi[(size_t)TKN * HID];
__device__ __align__(16) __nv_bfloat16 g_x_lo[(size_t)TKN * HID];
__device__ __align__(16) __nv_bfloat16 g_wfc_hi[(size_t)NE * INTR * HID];
__device__ __align__(16) __nv_bfloat16 g_wfc_lo[(size_t)NE * INTR * HID];
__device__ __align__(16) __nv_bfloat16 g_wpj_hi[(size_t)NE * HID * INTR];
__device__ __align__(16) __nv_bfloat16 g_wpj_lo[(size_t)NE * HID * INTR];
__device__ __align__(16) __nv_bfloat16 g_wfcs_hi[(size_t)SINT * HID];
__device__ __align__(16) __nv_bfloat16 g_wfcs_lo[(size_t)SINT * HID];
__device__ __align__(16) __nv_bfloat16 g_wpjs_hi[(size_t)HID * SINT];
__device__ __align__(16) __nv_bfloat16 g_wpjs_lo[(size_t)HID * SINT];
__device__ __align__(16) __nv_bfloat16 g_h_hi[(size_t)TKN * TOPK * INTR];
__device__ __align__(16) __nv_bfloat16 g_h_lo[(size_t)TKN * TOPK * INTR];
__device__ __align__(16) __nv_bfloat16 g_hs_hi[(size_t)TKN * SINT];
__device__ __align__(16) __nv_bfloat16 g_hs_lo[(size_t)TKN * SINT];
__device__ __align__(16) float g_partial[(size_t)TKN * TOPK * HID];

__device__ __forceinline__ float gelu_exact(float x) {
    return 0.5f * x * (1.0f + erff(x * 0.7071067811865476f));
}

// ===================== PTX helpers (base-target only) =====================
__device__ __forceinline__ uint32_t smem_to_u32(const void* p) {
    uint32_t a;
    asm("{ .reg .u64 t; cvta.to.shared.u64 t, %1; cvt.u32.u64 %0, t; }" : "=r"(a) : "l"(p));
    return a;
}
__device__ __forceinline__ void cp_async16(uint32_t dst, const void* src, uint32_t sz) {
    asm volatile(
        "{ .reg .u64 g; cvta.to.global.u64 g, %1;\n\t"
        "cp.async.cg.shared.global [%0], [g], 16, %2; }"
        :: "r"(dst), "l"(src), "r"(sz));
}
#define CP_COMMIT() asm volatile("cp.async.commit_group;" ::: "memory")
#define CP_WAIT(n)  asm volatile("cp.async.wait_group %0;" :: "n"(n) : "memory")

__device__ __forceinline__ void ldsm4(uint32_t& r0, uint32_t& r1, uint32_t& r2, uint32_t& r3,
                                      uint32_t addr) {
    asm volatile("ldmatrix.sync.aligned.m8n8.x4.shared.b16 {%0,%1,%2,%3}, [%4];"
        : "=r"(r0), "=r"(r1), "=r"(r2), "=r"(r3) : "r"(addr));
}
__device__ __forceinline__ void mma16816(float* c, const uint32_t* a, const uint32_t* b) {
    asm volatile(
        "mma.sync.aligned.m16n8k16.row.col.f32.bf16.bf16.f32 "
        "{%0,%1,%2,%3}, {%4,%5,%6,%7}, {%8,%9}, {%0,%1,%2,%3};"
        : "+f"(c[0]), "+f"(c[1]), "+f"(c[2]), "+f"(c[3])
        : "r"(a[0]), "r"(a[1]), "r"(a[2]), "r"(a[3]), "r"(b[0]), "r"(b[1]));
}

// swizzled smem layout: 128 rows x 64B (4 chunks of 16B), conflict-free for
// both cp.async stores and ldmatrix reads.
__device__ __forceinline__ uint32_t swz(int r, int c) {
    return (uint32_t)(r * 64 + ((c ^ ((r >> 1) & 3)) << 4));
}

// ===================== small kernels =====================
__global__ void init_kernel() {
    int i = threadIdx.x;
    if (i < NE) g_counts[i] = 0;
}

__global__ void router_kernel(const float* __restrict__ x, const float* __restrict__ wg) {
    __shared__ float s_wg[NE * HID];
    int tid = threadIdx.x;
    for (int i = tid; i < NE * HID; i += blockDim.x) s_wg[i] = wg[i];
    __syncthreads();
    int warp = tid >> 5, lane = tid & 31;
    int t = blockIdx.x * (blockDim.x >> 5) + warp;
    if (t >= TKN) return;
    float acc[NE];
#pragma unroll
    for (int e = 0; e < NE; e++) acc[e] = 0.0f;
    const float* xp = x + (size_t)t * HID;
    for (int k = lane; k < HID; k += 32) {
        float xv = xp[k];
#pragma unroll
        for (int e = 0; e < NE; e++) acc[e] = fmaf(xv, s_wg[e * HID + k], acc[e]);
    }
#pragma unroll
    for (int e = 0; e < NE; e++) {
#pragma unroll
        for (int o = 16; o > 0; o >>= 1) acc[e] += __shfl_xor_sync(0xffffffffu, acc[e], o);
    }
    if (lane == 0) {
        int i0 = 0; float v0 = acc[0];
#pragma unroll
        for (int e = 1; e < NE; e++) { if (acc[e] > v0) { v0 = acc[e]; i0 = e; } }
        int i1 = -1; float v1 = -1e30f;
#pragma unroll
        for (int e = 0; e < NE; e++) { if (e != i0 && acc[e] > v1) { v1 = acc[e]; i1 = e; } }
        float e1 = expf(v1 - v0);
        float denom = 1.0f + e1;
        g_topidx[t * 2 + 0] = i0;  g_topgate[t * 2 + 0] = 1.0f / denom;
        g_topidx[t * 2 + 1] = i1;  g_topgate[t * 2 + 1] = e1 / denom;
        atomicAdd(&g_counts[i0], 1);
        atomicAdd(&g_counts[i1], 1);
    }
}

__global__ void prefix_kernel() {
    if (threadIdx.x == 0) {
        int s = 0;
        for (int e = 0; e < NE; e++) { g_offsets[e] = s; s += g_counts[e]; g_cursor[e] = 0; }
    }
}

__global__ void scatter_kernel() {
    int t = blockIdx.x * blockDim.x + threadIdx.x;
    if (t >= TKN) return;
#pragma unroll
    for (int k = 0; k < TOPK; k++) {
        int e = g_topidx[t * 2 + k];
        int slot = atomicAdd(&g_cursor[e], 1);
        int pos = g_offsets[e] + slot;
        g_tok[pos] = t;
        g_gate[pos] = g_topgate[t * 2 + k];
        g_slot_of[t * 2 + k] = pos;
    }
}

// fp32 -> bf16 (hi) + bf16 residual (lo)
__global__ void split_kernel(const float* __restrict__ src,
                             __nv_bfloat16* __restrict__ hi,
                             __nv_bfloat16* __restrict__ lo, int n) {
    int i = (blockIdx.x * blockDim.x + threadIdx.x) * 4;
    if (i >= n) return;
    float4 v = *reinterpret_cast<const float4*>(src + i);
    __nv_bfloat16 h0 = __float2bfloat16(v.x), h1 = __float2bfloat16(v.y);
    __nv_bfloat16 h2 = __float2bfloat16(v.z), h3 = __float2bfloat16(v.w);
    __nv_bfloat16 l0 = __float2bfloat16(v.x - __bfloat162float(h0));
    __nv_bfloat16 l1 = __float2bfloat16(v.y - __bfloat162float(h1));
    __nv_bfloat16 l2 = __float2bfloat16(v.z - __bfloat162float(h2));
    __nv_bfloat16 l3 = __float2bfloat16(v.w - __bfloat162float(h3));
    uint2 hp, lp;
    hp.x = (uint32_t)__bfloat16_as_ushort(h0) | ((uint32_t)__bfloat16_as_ushort(h1) << 16);
    hp.y = (uint32_t)__bfloat16_as_ushort(h2) | ((uint32_t)__bfloat16_as_ushort(h3) << 16);
    lp.x = (uint32_t)__bfloat16_as_ushort(l0) | ((uint32_t)__bfloat16_as_ushort(l1) << 16);
    lp.y = (uint32_t)__bfloat16_as_ushort(l2) | ((uint32_t)__bfloat16_as_ushort(l3) << 16);
    *reinterpret_cast<uint2*>(hi + i) = hp;
    *reinterpret_cast<uint2*>(lo + i) = lp;
}

// ===================== mma.sync grouped GEMM =====================
// Block tile 128x128, BK=32 bf16. 8 warps (2 x 4), warp tile 64x32.
// 3-pass fp32 emulation: acc += Ahi*Bhi + Ahi*Blo + Alo*Bhi.
// Swizzled 64B-row smem tiles; 4-stage cp.async pipeline, 1 sync per k-iter.
#define TILE_B   8192
#define STAGE_B  32768
#define NSTAGE   4
#define SMEM_MMA (NSTAGE * STAGE_B)

template <int MODE>
__global__ void __launch_bounds__(256, 1) mma_gemm(float* __restrict__ outp)
{
    constexpr int KD = (MODE == 1) ? INTR : HID;
    constexpr int ND = (MODE == 0) ? INTR : ((MODE == 2) ? SINT : HID);
    constexpr int ITERS = KD / 32;

    int rows, base, e = 0;
    if (MODE <= 1) {
        e = blockIdx.z;
        rows = g_counts[e];
        base = g_offsets[e];
    } else { rows = TKN; base = 0; }
    const int bm = blockIdx.y;
    if (bm * 128 >= rows) return;
    const int bn = blockIdx.x;

    extern __shared__ char smem[];
    const uint32_t sb = smem_to_u32(smem);

    const int tid = threadIdx.x;
    const int wid = tid >> 5, lid = tid & 31;
    const int warp_m = wid & 1;      // 0..1 -> 64-row halves
    const int warp_n = wid >> 1;     // 0..3 -> 32-col quarters

    const __nv_bfloat16 *Ahi, *Alo, *Bhi, *Blo;
    if (MODE == 0)      { Ahi = g_x_hi;  Alo = g_x_lo; }
    else if (MODE == 1) { Ahi = g_h_hi;  Alo = g_h_lo; }
    else if (MODE == 2) { Ahi = g_x_hi;  Alo = g_x_lo; }
    else                { Ahi = g_hs_hi; Alo = g_hs_lo; }
    if (MODE == 0)      { Bhi = g_wfc_hi  + (size_t)e * INTR * HID; Blo = g_wfc_lo  + (size_t)e * INTR * HID; }
    else if (MODE == 1) { Bhi = g_wpj_hi  + (size_t)e * HID * INTR; Blo = g_wpj_lo  + (size_t)e * HID * INTR; }
    else if (MODE == 2) { Bhi = g_wfcs_hi; Blo = g_wfcs_lo; }
    else                { Bhi = g_wpjs_hi; Blo = g_wpjs_lo; }

    float acc[4][4][4];
#pragma unroll
    for (int i = 0; i < 4; i++)
#pragma unroll
        for (int j = 0; j < 4; j++)
#pragma unroll
            for (int q = 0; q < 4; q++) acc[i][j][q] = 0.0f;

    // precompute per-thread loader coords: 512 units = 128 rows x 4 chunks, x2
    const int lr0 = tid >> 2,         lc0 = tid & 3;
    const int lr1 = (tid + 256) >> 2, lc1 = (tid + 256) & 3;

    auto load_stage = [&](int it) {
        const int s = it & (NSTAGE - 1);
        const int k0 = it * 32;
        const uint32_t stBase = sb + (uint32_t)s * STAGE_B;
#pragma unroll
        for (int l = 0; l < 2; l++) {
            const int r  = l ? lr1 : lr0;
            const int ch = l ? lc1 : lc0;
            const uint32_t so = stBase + swz(r, ch);
            // A (hi + lo)
            int gm = bm * 128 + r;
            uint32_t szA = 16;
            size_t srow;
            if (MODE == 0) {
                if (gm < rows) srow = (size_t)g_tok[base + gm];
                else { srow = 0; szA = 0; }
            } else if (MODE == 1) {
                if (gm < rows) srow = (size_t)(base + gm);
                else { srow = (size_t)base; szA = 0; }
            } else srow = (size_t)gm;
            size_t goff = srow * KD + k0 + ch * 8;
            cp_async16(so,              Ahi + goff, szA);
            cp_async16(so + TILE_B,     Alo + goff, szA);
            // B (hi + lo)
            size_t boff = (size_t)(bn * 128 + r) * KD + k0 + ch * 8;
            cp_async16(so + 2 * TILE_B, Bhi + boff, 16);
            cp_async16(so + 3 * TILE_B, Blo + boff, 16);
        }
    };

    auto compute_stage = [&](int s) {
        const uint32_t aB = sb + (uint32_t)s * STAGE_B;
        const uint32_t bB = aB + 2 * TILE_B;
#pragma unroll
        for (int h = 0; h < 2; h++) {
            uint32_t ahi[4][4], alo[4][4], bhi[4][2], blo[4][2];
            const int a_ch = h * 2 + (lid >> 4);
            const int b_ch = h * 2 + ((lid >> 3) & 1);
#pragma unroll
            for (int i = 0; i < 4; i++) {
                int row = warp_m * 64 + i * 16 + (lid & 7) + ((lid >> 3) & 1) * 8;
                uint32_t ad = aB + swz(row, a_ch);
                ldsm4(ahi[i][0], ahi[i][1], ahi[i][2], ahi[i][3], ad);
                ldsm4(alo[i][0], alo[i][1], alo[i][2], alo[i][3], ad + TILE_B);
            }
#pragma unroll
            for (int jj = 0; jj < 2; jj++) {
                int nrow = warp_n * 32 + jj * 16 + ((lid >> 4) & 1) * 8 + (lid & 7);
                uint32_t bd = bB + swz(nrow, b_ch);
                uint32_t r0, r1, r2, r3;
                ldsm4(r0, r1, r2, r3, bd);
                bhi[2 * jj][0] = r0; bhi[2 * jj][1] = r1;
                bhi[2 * jj + 1][0] = r2; bhi[2 * jj + 1][1] = r3;
                ldsm4(r0, r1, r2, r3, bd + TILE_B);
                blo[2 * jj][0] = r0; blo[2 * jj][1] = r1;
                blo[2 * jj + 1][0] = r2; blo[2 * jj + 1][1] = r3;
            }
#pragma unroll
            for (int i = 0; i < 4; i++)
#pragma unroll
                for (int j = 0; j < 4; j++) {
                    mma16816(acc[i][j], ahi[i], bhi[j]);
                    mma16816(acc[i][j], ahi[i], blo[j]);
                    mma16816(acc[i][j], alo[i], bhi[j]);
                }
        }
    };

    // -------- 4-stage pipeline, single sync per iteration --------
    load_stage(0); CP_COMMIT();
    load_stage(1); CP_COMMIT();
    load_stage(2); CP_COMMIT();
#pragma unroll 1
    for (int it = 0; it < ITERS; ++it) {
        CP_WAIT(2);
        __syncthreads();
        if (it + 3 < ITERS) load_stage(it + 3);
        CP_COMMIT();
        compute_stage(it & (NSTAGE - 1));
    }

    // -------- epilogue --------
    const int g = lid >> 2, t4 = lid & 3;
#pragma unroll
    for (int i = 0; i < 4; i++) {
#pragma unroll
        for (int half = 0; half < 2; half++) {
            int row = bm * 128 + warp_m * 64 + i * 16 + g + half * 8;
            if (row >= rows) continue;
            float gate = 1.0f;
            if (MODE == 1) gate = g_gate[base + row];
#pragma unroll
            for (int j = 0; j < 4; j++) {
                float c0 = acc[i][j][half * 2 + 0];
                float c1 = acc[i][j][half * 2 + 1];
                int col = bn * 128 + warp_n * 32 + j * 8 + t4 * 2;
                if (MODE == 0 || MODE == 2) {
                    float f0 = gelu_exact(c0), f1 = gelu_exact(c1);
                    __nv_bfloat16 h0 = __float2bfloat16(f0);
                    __nv_bfloat16 h1 = __float2bfloat16(f1);
                    __nv_bfloat16 l0 = __float2bfloat16(f0 - __bfloat162float(h0));
                    __nv_bfloat16 l1 = __float2bfloat16(f1 - __bfloat162float(h1));
                    uint32_t hp = (uint32_t)__bfloat16_as_ushort(h0) | ((uint32_t)__bfloat16_as_ushort(h1) << 16);
                    uint32_t lp = (uint32_t)__bfloat16_as_ushort(l0) | ((uint32_t)__bfloat16_as_ushort(l1) << 16);
                    __nv_bfloat16* Hh = (MODE == 0) ? g_h_hi : g_hs_hi;
                    __nv_bfloat16* Hl = (MODE == 0) ? g_h_lo : g_hs_lo;
                    size_t off = (MODE == 0) ? ((size_t)(base + row) * ND + col)
                                             : ((size_t)row * ND + col);
                    *reinterpret_cast<uint32_t*>(Hh + off) = hp;
                    *reinterpret_cast<uint32_t*>(Hl + off) = lp;
                } else if (MODE == 1) {
                    size_t off = (size_t)(base + row) * HID + col;
                    float2 v = make_float2(gate * c0, gate * c1);
                    *reinterpret_cast<float2*>(g_partial + off) = v;
                } else {
                    size_t off = (size_t)row * HID + col;
                    float2 v = make_float2(c0, c1);
                    *reinterpret_cast<float2*>(outp + off) = v;
                }
            }
        }
    }
}

// ---------------- combine ----------------
__global__ void combine_kernel(float* __restrict__ out) {
    constexpr int NV = HID / 4;
    int idx = blockIdx.x * blockDim.x + threadIdx.x;
    if (idx >= TKN * NV) return;
    int t = idx / NV, n4 = idx % NV;
    int s0 = g_slot_of[t * 2 + 0];
    int s1 = g_slot_of[t * 2 + 1];
    float4 o = reinterpret_cast<float4*>(out)[idx];
    const float4* P = reinterpret_cast<const float4*>(g_partial);
    float4 p0 = P[(size_t)s0 * NV + n4];
    float4 p1 = P[(size_t)s1 * NV + n4];
    o.x += p0.x + p1.x;
    o.y += p0.y + p1.y;
    o.z += p0.z + p1.z;
    o.w += p0.w + p1.w;
    reinterpret_cast<float4*>(out)[idx] = o;
}

// ===================== launch =====================
extern "C" void kernel_launch(void* const* d_in, const int* in_sizes, int n_in,
                              void* d_out, int out_size) {
    (void)in_sizes; (void)n_in; (void)out_size;
    const float* x      = (const float*)d_in[0];
    const float* wg     = (const float*)d_in[1];
    const float* wfc    = (const float*)d_in[2];
    const float* wproj  = (const float*)d_in[3];
    const float* wfcs   = (const float*)d_in[4];
    const float* wprojs = (const float*)d_in[5];
    float* out = (float*)d_out;

    static bool attr_set = false;
    if (!attr_set) {
        cudaFuncSetAttribute(mma_gemm<0>, cudaFuncAttributeMaxDynamicSharedMemorySize, SMEM_MMA);
        cudaFuncSetAttribute(mma_gemm<1>, cudaFuncAttributeMaxDynamicSharedMemorySize, SMEM_MMA);
        cudaFuncSetAttribute(mma_gemm<2>, cudaFuncAttributeMaxDynamicSharedMemorySize, SMEM_MMA);
        cudaFuncSetAttribute(mma_gemm<3>, cudaFuncAttributeMaxDynamicSharedMemorySize, SMEM_MMA);
        attr_set = true;
    }

    init_kernel<<<1, 32>>>();
    router_kernel<<<TKN / 8, 256>>>(x, wg);
    prefix_kernel<<<1, 32>>>();
    scatter_kernel<<<TKN / 256, 256>>>();

    {
        __nv_bfloat16 *hi, *lo;
        cudaGetSymbolAddress((void**)&hi, g_x_hi);  cudaGetSymbolAddress((void**)&lo, g_x_lo);
        split_kernel<<<(TKN * HID) / 1024, 256>>>(x, hi, lo, TKN * HID);
        cudaGetSymbolAddress((void**)&hi, g_wfc_hi); cudaGetSymbolAddress((void**)&lo, g_wfc_lo);
        split_kernel<<<(NE * INTR * HID) / 1024, 256>>>(wfc, hi, lo, NE * INTR * HID);
        cudaGetSymbolAddress((void**)&hi, g_wpj_hi); cudaGetSymbolAddress((void**)&lo, g_wpj_lo);
        split_kernel<<<(NE * HID * INTR) / 1024, 256>>>(wproj, hi, lo, NE * HID * INTR);
        cudaGetSymbolAddress((void**)&hi, g_wfcs_hi); cudaGetSymbolAddress((void**)&lo, g_wfcs_lo);
        split_kernel<<<(SINT * HID) / 1024, 256>>>(wfcs, hi, lo, SINT * HID);
        cudaGetSymbolAddress((void**)&hi, g_wpjs_hi); cudaGetSymbolAddress((void**)&lo, g_wpjs_lo);
        split_kernel<<<(HID * SINT) / 1024, 256>>>(wprojs, hi, lo, HID * SINT);
    }

    // expert fc: gathered x -> gelu -> g_h (bf16 hi/lo)
    mma_gemm<0><<<dim3(INTR / 128, TKN * TOPK / 128, NE), 256, SMEM_MMA>>>(nullptr);
    // shared fc: x -> gelu -> g_hs
    mma_gemm<2><<<dim3(SINT / 128, TKN / 128, 1), 256, SMEM_MMA>>>(nullptr);
    // expert proj: g_h -> gate-scaled -> g_partial
    mma_gemm<1><<<dim3(HID / 128, TKN * TOPK / 128, NE), 256, SMEM_MMA>>>(nullptr);
    // shared proj: g_hs -> out
    mma_gemm<3><<<dim3(HID / 128, TKN / 128, 1), 256, SMEM_MMA>>>(out);

    combine_kernel<<<(TKN * (HID / 4)) / 256, 256>>>(out);
}

// round 5
// speedup vs baseline: 2.9099x; 1.1730x over previous
#include <cuda_runtime.h>
#include <cuda_bf16.h>
#include <math.h>
#include <stdint.h>

#define TKN   8192
#define HID   1024
#define NE    8
#define TOPK  2
#define INTR  2048
#define SINT  1024

// ===================== scratch (device globals; no allocations) =====================
__device__ int   g_counts[NE];
__device__ int   g_offsets[NE];
__device__ int   g_cursor[NE];
__device__ __align__(16) int   g_tok[TKN * TOPK];
__device__ __align__(16) float g_gate[TKN * TOPK];
__device__ __align__(16) int   g_slot_of[TKN * TOPK];
__device__ __align__(16) int   g_topidx[TKN * TOPK];
__device__ __align__(16) float g_topgate[TKN * TOPK];

__device__ __align__(16) __nv_bfloat16 g_x_hi[(size_t)TKN * HID];
__device__ __align__(16) __nv_bfloat16 g_x_lo[(size_t)TKN * HID];
__device__ __align__(16) __nv_bfloat16 g_wfc_hi[(size_t)NE * INTR * HID];
__device__ __align__(16) __nv_bfloat16 g_wfc_lo[(size_t)NE * INTR * HID];
__device__ __align__(16) __nv_bfloat16 g_wpj_hi[(size_t)NE * HID * INTR];
__device__ __align__(16) __nv_bfloat16 g_wpj_lo[(size_t)NE * HID * INTR];
__device__ __align__(16) __nv_bfloat16 g_wfcs_hi[(size_t)SINT * HID];
__device__ __align__(16) __nv_bfloat16 g_wfcs_lo[(size_t)SINT * HID];
__device__ __align__(16) __nv_bfloat16 g_wpjs_hi[(size_t)HID * SINT];
__device__ __align__(16) __nv_bfloat16 g_wpjs_lo[(size_t)HID * SINT];
__device__ __align__(16) __nv_bfloat16 g_h_hi[(size_t)TKN * TOPK * INTR];
__device__ __align__(16) __nv_bfloat16 g_h_lo[(size_t)TKN * TOPK * INTR];
__device__ __align__(16) __nv_bfloat16 g_hs_hi[(size_t)TKN * SINT];
__device__ __align__(16) __nv_bfloat16 g_hs_lo[(size_t)TKN * SINT];
__device__ __align__(16) float g_partial[(size_t)TKN * TOPK * HID];

__device__ __forceinline__ float gelu_exact(float x) {
    return 0.5f * x * (1.0f + erff(x * 0.7071067811865476f));
}

// ===================== PTX helpers (base-target only) =====================
__device__ __forceinline__ uint32_t smem_to_u32(const void* p) {
    uint32_t a;
    asm("{ .reg .u64 t; cvta.to.shared.u64 t, %1; cvt.u32.u64 %0, t; }" : "=r"(a) : "l"(p));
    return a;
}
__device__ __forceinline__ void cp_async16(uint32_t dst, const void* src, uint32_t sz) {
    asm volatile(
        "{ .reg .u64 g; cvta.to.global.u64 g, %1;\n\t"
        "cp.async.cg.shared.global [%0], [g], 16, %2; }"
        :: "r"(dst), "l"(src), "r"(sz));
}
#define CP_COMMIT() asm volatile("cp.async.commit_group;" ::: "memory")
#define CP_WAIT(n)  asm volatile("cp.async.wait_group %0;" :: "n"(n) : "memory")

__device__ __forceinline__ void ldsm4(uint32_t& r0, uint32_t& r1, uint32_t& r2, uint32_t& r3,
                                      uint32_t addr) {
    asm volatile("ldmatrix.sync.aligned.m8n8.x4.shared.b16 {%0,%1,%2,%3}, [%4];"
        : "=r"(r0), "=r"(r1), "=r"(r2), "=r"(r3) : "r"(addr));
}
__device__ __forceinline__ void mma16816(float* c, const uint32_t* a, const uint32_t* b) {
    asm volatile(
        "mma.sync.aligned.m16n8k16.row.col.f32.bf16.bf16.f32 "
        "{%0,%1,%2,%3}, {%4,%5,%6,%7}, {%8,%9}, {%0,%1,%2,%3};"
        : "+f"(c[0]), "+f"(c[1]), "+f"(c[2]), "+f"(c[3])
        : "r"(a[0]), "r"(a[1]), "r"(a[2]), "r"(a[3]), "r"(b[0]), "r"(b[1]));
}

// swizzled smem layout: rows x 64B (4 chunks of 16B), conflict-free for
// both cp.async stores and ldmatrix reads.
__device__ __forceinline__ uint32_t swz(int r, int c) {
    return (uint32_t)(r * 64 + ((c ^ ((r >> 1) & 3)) << 4));
}

// ===================== small kernels =====================
__global__ void init_kernel() {
    int i = threadIdx.x;
    if (i < NE) g_counts[i] = 0;
}

__global__ void router_kernel(const float* __restrict__ x, const float* __restrict__ wg) {
    __shared__ float s_wg[NE * HID];
    int tid = threadIdx.x;
    for (int i = tid; i < NE * HID; i += blockDim.x) s_wg[i] = wg[i];
    __syncthreads();
    int warp = tid >> 5, lane = tid & 31;
    int t = blockIdx.x * (blockDim.x >> 5) + warp;
    if (t >= TKN) return;
    float acc[NE];
#pragma unroll
    for (int e = 0; e < NE; e++) acc[e] = 0.0f;
    const float* xp = x + (size_t)t * HID;
    for (int k = lane; k < HID; k += 32) {
        float xv = xp[k];
#pragma unroll
        for (int e = 0; e < NE; e++) acc[e] = fmaf(xv, s_wg[e * HID + k], acc[e]);
    }
#pragma unroll
    for (int e = 0; e < NE; e++) {
#pragma unroll
        for (int o = 16; o > 0; o >>= 1) acc[e] += __shfl_xor_sync(0xffffffffu, acc[e], o);
    }
    if (lane == 0) {
        int i0 = 0; float v0 = acc[0];
#pragma unroll
        for (int e = 1; e < NE; e++) { if (acc[e] > v0) { v0 = acc[e]; i0 = e; } }
        int i1 = -1; float v1 = -1e30f;
#pragma unroll
        for (int e = 0; e < NE; e++) { if (e != i0 && acc[e] > v1) { v1 = acc[e]; i1 = e; } }
        float e1 = expf(v1 - v0);
        float denom = 1.0f + e1;
        g_topidx[t * 2 + 0] = i0;  g_topgate[t * 2 + 0] = 1.0f / denom;
        g_topidx[t * 2 + 1] = i1;  g_topgate[t * 2 + 1] = e1 / denom;
        atomicAdd(&g_counts[i0], 1);
        atomicAdd(&g_counts[i1], 1);
    }
}

__global__ void prefix_kernel() {
    if (threadIdx.x == 0) {
        int s = 0;
        for (int e = 0; e < NE; e++) { g_offsets[e] = s; s += g_counts[e]; g_cursor[e] = 0; }
    }
}

__global__ void scatter_kernel() {
    int t = blockIdx.x * blockDim.x + threadIdx.x;
    if (t >= TKN) return;
#pragma unroll
    for (int k = 0; k < TOPK; k++) {
        int e = g_topidx[t * 2 + k];
        int slot = atomicAdd(&g_cursor[e], 1);
        int pos = g_offsets[e] + slot;
        g_tok[pos] = t;
        g_gate[pos] = g_topgate[t * 2 + k];
        g_slot_of[t * 2 + k] = pos;
    }
}

// fp32 -> bf16 (hi) + bf16 residual (lo)
__global__ void split_kernel(const float* __restrict__ src,
                             __nv_bfloat16* __restrict__ hi,
                             __nv_bfloat16* __restrict__ lo, int n) {
    int i = (blockIdx.x * blockDim.x + threadIdx.x) * 4;
    if (i >= n) return;
    float4 v = *reinterpret_cast<const float4*>(src + i);
    __nv_bfloat16 h0 = __float2bfloat16(v.x), h1 = __float2bfloat16(v.y);
    __nv_bfloat16 h2 = __float2bfloat16(v.z), h3 = __float2bfloat16(v.w);
    __nv_bfloat16 l0 = __float2bfloat16(v.x - __bfloat162float(h0));
    __nv_bfloat16 l1 = __float2bfloat16(v.y - __bfloat162float(h1));
    __nv_bfloat16 l2 = __float2bfloat16(v.z - __bfloat162float(h2));
    __nv_bfloat16 l3 = __float2bfloat16(v.w - __bfloat162float(h3));
    uint2 hp, lp;
    hp.x = (uint32_t)__bfloat16_as_ushort(h0) | ((uint32_t)__bfloat16_as_ushort(h1) << 16);
    hp.y = (uint32_t)__bfloat16_as_ushort(h2) | ((uint32_t)__bfloat16_as_ushort(h3) << 16);
    lp.x = (uint32_t)__bfloat16_as_ushort(l0) | ((uint32_t)__bfloat16_as_ushort(l1) << 16);
    lp.y = (uint32_t)__bfloat16_as_ushort(l2) | ((uint32_t)__bfloat16_as_ushort(l3) << 16);
    *reinterpret_cast<uint2*>(hi + i) = hp;
    *reinterpret_cast<uint2*>(lo + i) = lp;
}

// ===================== mma.sync grouped GEMM =====================
// Block tile 128x128, BK=32 bf16. 8 warps (2 x 4), warp tile 64x32.
// 3-pass fp32 emulation: acc += Ahi*Bhi + Ahi*Blo + Alo*Bhi.
// Swizzled 64B-row smem; 3-stage cp.async pipeline; 2 CTAs/SM for latency hiding.
#define TILE_B   8192
#define STAGE_B  32768
#define NSTAGE   3
#define SMEM_MMA (NSTAGE * STAGE_B)

template <int MODE>
__global__ void __launch_bounds__(256, 2) mma_gemm(float* __restrict__ outp)
{
    constexpr int KD = (MODE == 1) ? INTR : HID;
    constexpr int ND = (MODE == 0) ? INTR : ((MODE == 2) ? SINT : HID);
    constexpr int ITERS = KD / 32;

    int rows, base, e = 0;
    if (MODE <= 1) {
        e = blockIdx.z;
        rows = g_counts[e];
        base = g_offsets[e];
    } else { rows = TKN; base = 0; }
    const int bm = blockIdx.y;
    if (bm * 128 >= rows) return;
    const int bn = blockIdx.x;

    extern __shared__ char smem[];
    const uint32_t sb = smem_to_u32(smem);

    const int tid = threadIdx.x;
    const int wid = tid >> 5, lid = tid & 31;
    const int warp_m = wid & 1;      // 0..1 -> 64-row halves
    const int warp_n = wid >> 1;     // 0..3 -> 32-col quarters

    const __nv_bfloat16 *Ahi, *Alo, *Bhi, *Blo;
    if (MODE == 0)      { Ahi = g_x_hi;  Alo = g_x_lo; }
    else if (MODE == 1) { Ahi = g_h_hi;  Alo = g_h_lo; }
    else if (MODE == 2) { Ahi = g_x_hi;  Alo = g_x_lo; }
    else                { Ahi = g_hs_hi; Alo = g_hs_lo; }
    if (MODE == 0)      { Bhi = g_wfc_hi  + (size_t)e * INTR * HID; Blo = g_wfc_lo  + (size_t)e * INTR * HID; }
    else if (MODE == 1) { Bhi = g_wpj_hi  + (size_t)e * HID * INTR; Blo = g_wpj_lo  + (size_t)e * HID * INTR; }
    else if (MODE == 2) { Bhi = g_wfcs_hi; Blo = g_wfcs_lo; }
    else                { Bhi = g_wpjs_hi; Blo = g_wpjs_lo; }

    float acc[4][4][4];
#pragma unroll
    for (int i = 0; i < 4; i++)
#pragma unroll
        for (int j = 0; j < 4; j++)
#pragma unroll
            for (int q = 0; q < 4; q++) acc[i][j][q] = 0.0f;

    const int lr0 = tid >> 2,         lc0 = tid & 3;
    const int lr1 = (tid + 256) >> 2, lc1 = (tid + 256) & 3;

    auto load_stage = [&](int it) {
        const int s = it % NSTAGE;
        const int k0 = it * 32;
        const uint32_t stBase = sb + (uint32_t)s * STAGE_B;
#pragma unroll
        for (int l = 0; l < 2; l++) {
            const int r  = l ? lr1 : lr0;
            const int ch = l ? lc1 : lc0;
            const uint32_t so = stBase + swz(r, ch);
            int gm = bm * 128 + r;
            uint32_t szA = 16;
            size_t srow;
            if (MODE == 0) {
                if (gm < rows) srow = (size_t)g_tok[base + gm];
                else { srow = 0; szA = 0; }
            } else if (MODE == 1) {
                if (gm < rows) srow = (size_t)(base + gm);
                else { srow = (size_t)base; szA = 0; }
            } else srow = (size_t)gm;
            size_t goff = srow * KD + k0 + ch * 8;
            cp_async16(so,              Ahi + goff, szA);
            cp_async16(so + TILE_B,     Alo + goff, szA);
            size_t boff = (size_t)(bn * 128 + r) * KD + k0 + ch * 8;
            cp_async16(so + 2 * TILE_B, Bhi + boff, 16);
            cp_async16(so + 3 * TILE_B, Blo + boff, 16);
        }
    };

    // register-lean compute: a[] reused for ahi then alo; b1=bhi kept, b2=blo.
    auto compute_stage = [&](int s) {
        const uint32_t aB = sb + (uint32_t)s * STAGE_B;
        const uint32_t bB = aB + 2 * TILE_B;
#pragma unroll
        for (int h = 0; h < 2; h++) {
            uint32_t a[4][4], b1[4][2], b2[4][2];
            const int a_ch = h * 2 + (lid >> 4);
            const int b_ch = h * 2 + ((lid >> 3) & 1);
            const int arow0 = warp_m * 64 + (lid & 7) + ((lid >> 3) & 1) * 8;
            // --- pass 1: a_hi x b_hi ---
#pragma unroll
            for (int i = 0; i < 4; i++) {
                uint32_t ad = aB + swz(arow0 + i * 16, a_ch);
                ldsm4(a[i][0], a[i][1], a[i][2], a[i][3], ad);
            }
#pragma unroll
            for (int jj = 0; jj < 2; jj++) {
                int nrow = warp_n * 32 + jj * 16 + ((lid >> 4) & 1) * 8 + (lid & 7);
                uint32_t bd = bB + swz(nrow, b_ch);
                uint32_t r0, r1, r2, r3;
                ldsm4(r0, r1, r2, r3, bd);
                b1[2 * jj][0] = r0; b1[2 * jj][1] = r1;
                b1[2 * jj + 1][0] = r2; b1[2 * jj + 1][1] = r3;
            }
#pragma unroll
            for (int i = 0; i < 4; i++)
#pragma unroll
                for (int j = 0; j < 4; j++) mma16816(acc[i][j], a[i], b1[j]);
            // --- pass 2: a_hi x b_lo ---
#pragma unroll
            for (int jj = 0; jj < 2; jj++) {
                int nrow = warp_n * 32 + jj * 16 + ((lid >> 4) & 1) * 8 + (lid & 7);
                uint32_t bd = bB + TILE_B + swz(nrow, b_ch);
                uint32_t r0, r1, r2, r3;
                ldsm4(r0, r1, r2, r3, bd);
                b2[2 * jj][0] = r0; b2[2 * jj][1] = r1;
                b2[2 * jj + 1][0] = r2; b2[2 * jj + 1][1] = r3;
            }
#pragma unroll
            for (int i = 0; i < 4; i++)
#pragma unroll
                for (int j = 0; j < 4; j++) mma16816(acc[i][j], a[i], b2[j]);
            // --- pass 3: a_lo x b_hi (a[] reused) ---
#pragma unroll
            for (int i = 0; i < 4; i++) {
                uint32_t ad = aB + TILE_B + swz(arow0 + i * 16, a_ch);
                ldsm4(a[i][0], a[i][1], a[i][2], a[i][3], ad);
            }
#pragma unroll
            for (int i = 0; i < 4; i++)
#pragma unroll
                for (int j = 0; j < 4; j++) mma16816(acc[i][j], a[i], b1[j]);
        }
    };

    // -------- 3-stage pipeline, single sync per iteration --------
    load_stage(0); CP_COMMIT();
    load_stage(1); CP_COMMIT();
#pragma unroll 1
    for (int it = 0; it < ITERS; ++it) {
        CP_WAIT(1);
        __syncthreads();
        if (it + 2 < ITERS) load_stage(it + 2);
        CP_COMMIT();
        compute_stage(it % NSTAGE);
    }

    // -------- epilogue --------
    const int g = lid >> 2, t4 = lid & 3;
#pragma unroll
    for (int i = 0; i < 4; i++) {
#pragma unroll
        for (int half = 0; half < 2; half++) {
            int row = bm * 128 + warp_m * 64 + i * 16 + g + half * 8;
            if (row >= rows) continue;
            float gate = 1.0f;
            if (MODE == 1) gate = g_gate[base + row];
#pragma unroll
            for (int j = 0; j < 4; j++) {
                float c0 = acc[i][j][half * 2 + 0];
                float c1 = acc[i][j][half * 2 + 1];
                int col = bn * 128 + warp_n * 32 + j * 8 + t4 * 2;
                if (MODE == 0 || MODE == 2) {
                    float f0 = gelu_exact(c0), f1 = gelu_exact(c1);
                    __nv_bfloat16 h0 = __float2bfloat16(f0);
                    __nv_bfloat16 h1 = __float2bfloat16(f1);
                    __nv_bfloat16 l0 = __float2bfloat16(f0 - __bfloat162float(h0));
                    __nv_bfloat16 l1 = __float2bfloat16(f1 - __bfloat162float(h1));
                    uint32_t hp = (uint32_t)__bfloat16_as_ushort(h0) | ((uint32_t)__bfloat16_as_ushort(h1) << 16);
                    uint32_t lp = (uint32_t)__bfloat16_as_ushort(l0) | ((uint32_t)__bfloat16_as_ushort(l1) << 16);
                    __nv_bfloat16* Hh = (MODE == 0) ? g_h_hi : g_hs_hi;
                    __nv_bfloat16* Hl = (MODE == 0) ? g_h_lo : g_hs_lo;
                    size_t off = (MODE == 0) ? ((size_t)(base + row) * ND + col)
                                             : ((size_t)row * ND + col);
                    *reinterpret_cast<uint32_t*>(Hh + off) = hp;
                    *reinterpret_cast<uint32_t*>(Hl + off) = lp;
                } else if (MODE == 1) {
                    size_t off = (size_t)(base + row) * HID + col;
                    float2 v = make_float2(gate * c0, gate * c1);
                    *reinterpret_cast<float2*>(g_partial + off) = v;
                } else {
                    size_t off = (size_t)row * HID + col;
                    float2 v = make_float2(c0, c1);
                    *reinterpret_cast<float2*>(outp + off) = v;
                }
            }
        }
    }
}

// ---------------- combine ----------------
__global__ void combine_kernel(float* __restrict__ out) {
    constexpr int NV = HID / 4;
    int idx = blockIdx.x * blockDim.x + threadIdx.x;
    if (idx >= TKN * NV) return;
    int t = idx / NV, n4 = idx % NV;
    int s0 = g_slot_of[t * 2 + 0];
    int s1 = g_slot_of[t * 2 + 1];
    float4 o = reinterpret_cast<float4*>(out)[idx];
    const float4* P = reinterpret_cast<const float4*>(g_partial);
    float4 p0 = P[(size_t)s0 * NV + n4];
    float4 p1 = P[(size_t)s1 * NV + n4];
    o.x += p0.x + p1.x;
    o.y += p0.y + p1.y;
    o.z += p0.z + p1.z;
    o.w += p0.w + p1.w;
    reinterpret_cast<float4*>(out)[idx] = o;
}

// ===================== launch =====================
extern "C" void kernel_launch(void* const* d_in, const int* in_sizes, int n_in,
                              void* d_out, int out_size) {
    (void)in_sizes; (void)n_in; (void)out_size;
    const float* x      = (const float*)d_in[0];
    const float* wg     = (const float*)d_in[1];
    const float* wfc    = (const float*)d_in[2];
    const float* wproj  = (const float*)d_in[3];
    const float* wfcs   = (const float*)d_in[4];
    const float* wprojs = (const float*)d_in[5];
    float* out = (float*)d_out;

    static bool attr_set = false;
    if (!attr_set) {
        cudaFuncSetAttribute(mma_gemm<0>, cudaFuncAttributeMaxDynamicSharedMemorySize, SMEM_MMA);
        cudaFuncSetAttribute(mma_gemm<1>, cudaFuncAttributeMaxDynamicSharedMemorySize, SMEM_MMA);
        cudaFuncSetAttribute(mma_gemm<2>, cudaFuncAttributeMaxDynamicSharedMemorySize, SMEM_MMA);
        cudaFuncSetAttribute(mma_gemm<3>, cudaFuncAttributeMaxDynamicSharedMemorySize, SMEM_MMA);
        attr_set = true;
    }

    init_kernel<<<1, 32>>>();
    router_kernel<<<TKN / 8, 256>>>(x, wg);
    prefix_kernel<<<1, 32>>>();
    scatter_kernel<<<TKN / 256, 256>>>();

    {
        __nv_bfloat16 *hi, *lo;
        cudaGetSymbolAddress((void**)&hi, g_x_hi);  cudaGetSymbolAddress((void**)&lo, g_x_lo);
        split_kernel<<<(TKN * HID) / 1024, 256>>>(x, hi, lo, TKN * HID);
        cudaGetSymbolAddress((void**)&hi, g_wfc_hi); cudaGetSymbolAddress((void**)&lo, g_wfc_lo);
        split_kernel<<<(NE * INTR * HID) / 1024, 256>>>(wfc, hi, lo, NE * INTR * HID);
        cudaGetSymbolAddress((void**)&hi, g_wpj_hi); cudaGetSymbolAddress((void**)&lo, g_wpj_lo);
        split_kernel<<<(NE * HID * INTR) / 1024, 256>>>(wproj, hi, lo, NE * HID * INTR);
        cudaGetSymbolAddress((void**)&hi, g_wfcs_hi); cudaGetSymbolAddress((void**)&lo, g_wfcs_lo);
        split_kernel<<<(SINT * HID) / 1024, 256>>>(wfcs, hi, lo, SINT * HID);
        cudaGetSymbolAddress((void**)&hi, g_wpjs_hi); cudaGetSymbolAddress((void**)&lo, g_wpjs_lo);
        split_kernel<<<(HID * SINT) / 1024, 256>>>(wprojs, hi, lo, HID * SINT);
    }

    // expert fc: gathered x -> gelu -> g_h (bf16 hi/lo)
    mma_gemm<0><<<dim3(INTR / 128, TKN * TOPK / 128, NE), 256, SMEM_MMA>>>(nullptr);
    // shared fc: x -> gelu -> g_hs
    mma_gemm<2><<<dim3(SINT / 128, TKN / 128, 1), 256, SMEM_MMA>>>(nullptr);
    // expert proj: g_h -> gate-scaled -> g_partial
    mma_gemm<1><<<dim3(HID / 128, TKN * TOPK / 128, NE), 256, SMEM_MMA>>>(nullptr);
    // shared proj: g_hs -> out
    mma_gemm<3><<<dim3(HID / 128, TKN / 128, 1), 256, SMEM_MMA>>>(out);

    combine_kernel<<<(TKN * (HID / 4)) / 256, 256>>>(out);
}

// round 6
// speedup vs baseline: 3.9457x; 1.3559x over previous
#include <cuda_runtime.h>
#include <cuda_fp16.h>
#include <math.h>
#include <stdint.h>

#define TKN   8192
#define HID   1024
#define NE    8
#define TOPK  2
#define INTR  2048
#define SINT  1024

// ===================== scratch (device globals; no allocations) =====================
__device__ int   g_counts[NE];
__device__ int   g_offsets[NE];
__device__ int   g_cursor[NE];
__device__ __align__(16) int   g_tok[TKN * TOPK];
__device__ __align__(16) float g_gate[TKN * TOPK];
__device__ __align__(16) int   g_slot_of[TKN * TOPK];
__device__ __align__(16) int   g_topidx[TKN * TOPK];
__device__ __align__(16) float g_topgate[TKN * TOPK];

// activations: fp16 hi + fp16 residual (22-bit effective mantissa)
__device__ __align__(16) __half g_x_hi[(size_t)TKN * HID];
__device__ __align__(16) __half g_x_lo[(size_t)TKN * HID];
__device__ __align__(16) __half g_h_hi[(size_t)TKN * TOPK * INTR];
__device__ __align__(16) __half g_h_lo[(size_t)TKN * TOPK * INTR];
__device__ __align__(16) __half g_hs_hi[(size_t)TKN * SINT];
__device__ __align__(16) __half g_hs_lo[(size_t)TKN * SINT];
// weights: single fp16 (round-to-nearest)
__device__ __align__(16) __half g_wfc[(size_t)NE * INTR * HID];
__device__ __align__(16) __half g_wpj[(size_t)NE * HID * INTR];
__device__ __align__(16) __half g_wfcs[(size_t)SINT * HID];
__device__ __align__(16) __half g_wpjs[(size_t)HID * SINT];
__device__ __align__(16) float g_partial[(size_t)TKN * TOPK * HID];

__device__ __forceinline__ float gelu_exact(float x) {
    return 0.5f * x * (1.0f + erff(x * 0.7071067811865476f));
}

// ===================== PTX helpers (base-target only) =====================
__device__ __forceinline__ uint32_t smem_to_u32(const void* p) {
    uint32_t a;
    asm("{ .reg .u64 t; cvta.to.shared.u64 t, %1; cvt.u32.u64 %0, t; }" : "=r"(a) : "l"(p));
    return a;
}
__device__ __forceinline__ void cp_async16(uint32_t dst, const void* src, uint32_t sz) {
    asm volatile(
        "{ .reg .u64 g; cvta.to.global.u64 g, %1;\n\t"
        "cp.async.cg.shared.global [%0], [g], 16, %2; }"
        :: "r"(dst), "l"(src), "r"(sz));
}
#define CP_COMMIT() asm volatile("cp.async.commit_group;" ::: "memory")
#define CP_WAIT(n)  asm volatile("cp.async.wait_group %0;" :: "n"(n) : "memory")

__device__ __forceinline__ void ldsm4(uint32_t& r0, uint32_t& r1, uint32_t& r2, uint32_t& r3,
                                      uint32_t addr) {
    asm volatile("ldmatrix.sync.aligned.m8n8.x4.shared.b16 {%0,%1,%2,%3}, [%4];"
        : "=r"(r0), "=r"(r1), "=r"(r2), "=r"(r3) : "r"(addr));
}
__device__ __forceinline__ void mma16816(float* c, const uint32_t* a, const uint32_t* b) {
    asm volatile(
        "mma.sync.aligned.m16n8k16.row.col.f32.f16.f16.f32 "
        "{%0,%1,%2,%3}, {%4,%5,%6,%7}, {%8,%9}, {%0,%1,%2,%3};"
        : "+f"(c[0]), "+f"(c[1]), "+f"(c[2]), "+f"(c[3])
        : "r"(a[0]), "r"(a[1]), "r"(a[2]), "r"(a[3]), "r"(b[0]), "r"(b[1]));
}

// swizzled smem layout: rows x 64B (4 chunks of 16B), conflict-free for
// both cp.async stores and ldmatrix reads.
__device__ __forceinline__ uint32_t swz(int r, int c) {
    return (uint32_t)(r * 64 + ((c ^ ((r >> 1) & 3)) << 4));
}

// ===================== small kernels =====================
__global__ void init_kernel() {
    int i = threadIdx.x;
    if (i < NE) g_counts[i] = 0;
}

__global__ void router_kernel(const float* __restrict__ x, const float* __restrict__ wg) {
    __shared__ float s_wg[NE * HID];
    int tid = threadIdx.x;
    for (int i = tid; i < NE * HID; i += blockDim.x) s_wg[i] = wg[i];
    __syncthreads();
    int warp = tid >> 5, lane = tid & 31;
    int t = blockIdx.x * (blockDim.x >> 5) + warp;
    if (t >= TKN) return;
    float acc[NE];
#pragma unroll
    for (int e = 0; e < NE; e++) acc[e] = 0.0f;
    const float* xp = x + (size_t)t * HID;
    for (int k = lane; k < HID; k += 32) {
        float xv = xp[k];
#pragma unroll
        for (int e = 0; e < NE; e++) acc[e] = fmaf(xv, s_wg[e * HID + k], acc[e]);
    }
#pragma unroll
    for (int e = 0; e < NE; e++) {
#pragma unroll
        for (int o = 16; o > 0; o >>= 1) acc[e] += __shfl_xor_sync(0xffffffffu, acc[e], o);
    }
    if (lane == 0) {
        int i0 = 0; float v0 = acc[0];
#pragma unroll
        for (int e = 1; e < NE; e++) { if (acc[e] > v0) { v0 = acc[e]; i0 = e; } }
        int i1 = -1; float v1 = -1e30f;
#pragma unroll
        for (int e = 0; e < NE; e++) { if (e != i0 && acc[e] > v1) { v1 = acc[e]; i1 = e; } }
        float e1 = expf(v1 - v0);
        float denom = 1.0f + e1;
        g_topidx[t * 2 + 0] = i0;  g_topgate[t * 2 + 0] = 1.0f / denom;
        g_topidx[t * 2 + 1] = i1;  g_topgate[t * 2 + 1] = e1 / denom;
        atomicAdd(&g_counts[i0], 1);
        atomicAdd(&g_counts[i1], 1);
    }
}

__global__ void prefix_kernel() {
    if (threadIdx.x == 0) {
        int s = 0;
        for (int e = 0; e < NE; e++) { g_offsets[e] = s; s += g_counts[e]; g_cursor[e] = 0; }
    }
}

__global__ void scatter_kernel() {
    int t = blockIdx.x * blockDim.x + threadIdx.x;
    if (t >= TKN) return;
#pragma unroll
    for (int k = 0; k < TOPK; k++) {
        int e = g_topidx[t * 2 + k];
        int slot = atomicAdd(&g_cursor[e], 1);
        int pos = g_offsets[e] + slot;
        g_tok[pos] = t;
        g_gate[pos] = g_topgate[t * 2 + k];
        g_slot_of[t * 2 + k] = pos;
    }
}

// fp32 -> fp16 hi + fp16 residual
__global__ void split_kernel(const float* __restrict__ src,
                             __half* __restrict__ hi,
                             __half* __restrict__ lo, int n) {
    int i = (blockIdx.x * blockDim.x + threadIdx.x) * 4;
    if (i >= n) return;
    float4 v = *reinterpret_cast<const float4*>(src + i);
    __half h0 = __float2half_rn(v.x), h1 = __float2half_rn(v.y);
    __half h2 = __float2half_rn(v.z), h3 = __float2half_rn(v.w);
    __half l0 = __float2half_rn(v.x - __half2float(h0));
    __half l1 = __float2half_rn(v.y - __half2float(h1));
    __half l2 = __float2half_rn(v.z - __half2float(h2));
    __half l3 = __float2half_rn(v.w - __half2float(h3));
    uint2 hp, lp;
    hp.x = (uint32_t)__half_as_ushort(h0) | ((uint32_t)__half_as_ushort(h1) << 16);
    hp.y = (uint32_t)__half_as_ushort(h2) | ((uint32_t)__half_as_ushort(h3) << 16);
    lp.x = (uint32_t)__half_as_ushort(l0) | ((uint32_t)__half_as_ushort(l1) << 16);
    lp.y = (uint32_t)__half_as_ushort(l2) | ((uint32_t)__half_as_ushort(l3) << 16);
    *reinterpret_cast<uint2*>(hi + i) = hp;
    *reinterpret_cast<uint2*>(lo + i) = lp;
}

// fp32 -> fp16 (weights)
__global__ void cvt_kernel(const float* __restrict__ src, __half* __restrict__ dst, int n) {
    int i = (blockIdx.x * blockDim.x + threadIdx.x) * 4;
    if (i >= n) return;
    float4 v = *reinterpret_cast<const float4*>(src + i);
    uint2 p;
    p.x = (uint32_t)__half_as_ushort(__float2half_rn(v.x)) |
          ((uint32_t)__half_as_ushort(__float2half_rn(v.y)) << 16);
    p.y = (uint32_t)__half_as_ushort(__float2half_rn(v.z)) |
          ((uint32_t)__half_as_ushort(__float2half_rn(v.w)) << 16);
    *reinterpret_cast<uint2*>(dst + i) = p;
}

// ===================== mma.sync grouped GEMM =====================
// Block tile 128x128, BK=32 fp16. 8 warps (2 x 4), warp tile 64x32.
// 2-pass fp32 emulation: acc = Ahi*B + Alo*B (A split fp16, B rounded fp16).
// Swizzled 64B-row smem; 4-stage cp.async pipeline; 2 CTAs/SM.
#define TILE_B   8192
#define STAGE_B  24576
#define NSTAGE   4
#define SMEM_MMA (NSTAGE * STAGE_B)

template <int MODE>
__global__ void __launch_bounds__(256, 2) mma_gemm(float* __restrict__ outp)
{
    constexpr int KD = (MODE == 1) ? INTR : HID;
    constexpr int ND = (MODE == 0) ? INTR : ((MODE == 2) ? SINT : HID);
    constexpr int ITERS = KD / 32;

    int rows, base, e = 0;
    if (MODE <= 1) {
        e = blockIdx.z;
        rows = g_counts[e];
        base = g_offsets[e];
    } else { rows = TKN; base = 0; }
    const int bm = blockIdx.y;
    if (bm * 128 >= rows) return;
    const int bn = blockIdx.x;

    extern __shared__ char smem[];
    const uint32_t sb = smem_to_u32(smem);

    const int tid = threadIdx.x;
    const int wid = tid >> 5, lid = tid & 31;
    const int warp_m = wid & 1;
    const int warp_n = wid >> 1;

    const __half *Ahi, *Alo, *B;
    if (MODE == 0)      { Ahi = g_x_hi;  Alo = g_x_lo; }
    else if (MODE == 1) { Ahi = g_h_hi;  Alo = g_h_lo; }
    else if (MODE == 2) { Ahi = g_x_hi;  Alo = g_x_lo; }
    else                { Ahi = g_hs_hi; Alo = g_hs_lo; }
    if (MODE == 0)      B = g_wfc  + (size_t)e * INTR * HID;
    else if (MODE == 1) B = g_wpj  + (size_t)e * HID * INTR;
    else if (MODE == 2) B = g_wfcs;
    else                B = g_wpjs;

    float acc[4][4][4];
#pragma unroll
    for (int i = 0; i < 4; i++)
#pragma unroll
        for (int j = 0; j < 4; j++)
#pragma unroll
            for (int q = 0; q < 4; q++) acc[i][j][q] = 0.0f;

    const int lr0 = tid >> 2,         lc0 = tid & 3;
    const int lr1 = (tid + 256) >> 2, lc1 = (tid + 256) & 3;

    auto load_stage = [&](int it) {
        const int s = it & (NSTAGE - 1);
        const int k0 = it * 32;
        const uint32_t stBase = sb + (uint32_t)s * STAGE_B;
#pragma unroll
        for (int l = 0; l < 2; l++) {
            const int r  = l ? lr1 : lr0;
            const int ch = l ? lc1 : lc0;
            const uint32_t so = stBase + swz(r, ch);
            int gm = bm * 128 + r;
            uint32_t szA = 16;
            size_t srow;
            if (MODE == 0) {
                if (gm < rows) srow = (size_t)g_tok[base + gm];
                else { srow = 0; szA = 0; }
            } else if (MODE == 1) {
                if (gm < rows) srow = (size_t)(base + gm);
                else { srow = (size_t)base; szA = 0; }
            } else srow = (size_t)gm;
            size_t goff = srow * KD + k0 + ch * 8;
            cp_async16(so,              Ahi + goff, szA);
            cp_async16(so + TILE_B,     Alo + goff, szA);
            size_t boff = (size_t)(bn * 128 + r) * KD + k0 + ch * 8;
            cp_async16(so + 2 * TILE_B, B + boff, 16);
        }
    };

    auto compute_stage = [&](int s) {
        const uint32_t aB = sb + (uint32_t)s * STAGE_B;
        const uint32_t bB = aB + 2 * TILE_B;
#pragma unroll
        for (int h = 0; h < 2; h++) {
            uint32_t a[4][4], b[4][2];
            const int a_ch = h * 2 + (lid >> 4);
            const int b_ch = h * 2 + ((lid >> 3) & 1);
            const int arow0 = warp_m * 64 + (lid & 7) + ((lid >> 3) & 1) * 8;
            // B fragments (shared by both passes)
#pragma unroll
            for (int jj = 0; jj < 2; jj++) {
                int nrow = warp_n * 32 + jj * 16 + ((lid >> 4) & 1) * 8 + (lid & 7);
                uint32_t bd = bB + swz(nrow, b_ch);
                uint32_t r0, r1, r2, r3;
                ldsm4(r0, r1, r2, r3, bd);
                b[2 * jj][0] = r0; b[2 * jj][1] = r1;
                b[2 * jj + 1][0] = r2; b[2 * jj + 1][1] = r3;
            }
            // pass 1: A_hi x B
#pragma unroll
            for (int i = 0; i < 4; i++) {
                uint32_t ad = aB + swz(arow0 + i * 16, a_ch);
                ldsm4(a[i][0], a[i][1], a[i][2], a[i][3], ad);
            }
#pragma unroll
            for (int i = 0; i < 4; i++)
#pragma unroll
                for (int j = 0; j < 4; j++) mma16816(acc[i][j], a[i], b[j]);
            // pass 2: A_lo x B (a[] reused)
#pragma unroll
            for (int i = 0; i < 4; i++) {
                uint32_t ad = aB + TILE_B + swz(arow0 + i * 16, a_ch);
                ldsm4(a[i][0], a[i][1], a[i][2], a[i][3], ad);
            }
#pragma unroll
            for (int i = 0; i < 4; i++)
#pragma unroll
                for (int j = 0; j < 4; j++) mma16816(acc[i][j], a[i], b[j]);
        }
    };

    // -------- 4-stage pipeline, single sync per iteration --------
    load_stage(0); CP_COMMIT();
    load_stage(1); CP_COMMIT();
    load_stage(2); CP_COMMIT();
#pragma unroll 1
    for (int it = 0; it < ITERS; ++it) {
        CP_WAIT(2);
        __syncthreads();
        if (it + 3 < ITERS) load_stage(it + 3);
        CP_COMMIT();
        compute_stage(it & (NSTAGE - 1));
    }

    // -------- epilogue --------
    const int g = lid >> 2, t4 = lid & 3;
#pragma unroll
    for (int i = 0; i < 4; i++) {
#pragma unroll
        for (int half = 0; half < 2; half++) {
            int row = bm * 128 + warp_m * 64 + i * 16 + g + half * 8;
            if (row >= rows) continue;
            float gate = 1.0f;
            if (MODE == 1) gate = g_gate[base + row];
#pragma unroll
            for (int j = 0; j < 4; j++) {
                float c0 = acc[i][j][half * 2 + 0];
                float c1 = acc[i][j][half * 2 + 1];
                int col = bn * 128 + warp_n * 32 + j * 8 + t4 * 2;
                if (MODE == 0 || MODE == 2) {
                    float f0 = gelu_exact(c0), f1 = gelu_exact(c1);
                    __half h0 = __float2half_rn(f0);
                    __half h1 = __float2half_rn(f1);
                    __half l0 = __float2half_rn(f0 - __half2float(h0));
                    __half l1 = __float2half_rn(f1 - __half2float(h1));
                    uint32_t hp = (uint32_t)__half_as_ushort(h0) | ((uint32_t)__half_as_ushort(h1) << 16);
                    uint32_t lp = (uint32_t)__half_as_ushort(l0) | ((uint32_t)__half_as_ushort(l1) << 16);
                    __half* Hh = (MODE == 0) ? g_h_hi : g_hs_hi;
                    __half* Hl = (MODE == 0) ? g_h_lo : g_hs_lo;
                    size_t off = (MODE == 0) ? ((size_t)(base + row) * ND + col)
                                             : ((size_t)row * ND + col);
                    *reinterpret_cast<uint32_t*>(Hh + off) = hp;
                    *reinterpret_cast<uint32_t*>(Hl + off) = lp;
                } else if (MODE == 1) {
                    size_t off = (size_t)(base + row) * HID + col;
                    float2 v = make_float2(gate * c0, gate * c1);
                    *reinterpret_cast<float2*>(g_partial + off) = v;
                } else {
                    size_t off = (size_t)row * HID + col;
                    float2 v = make_float2(c0, c1);
                    *reinterpret_cast<float2*>(outp + off) = v;
                }
            }
        }
    }
}

// ---------------- combine ----------------
__global__ void combine_kernel(float* __restrict__ out) {
    constexpr int NV = HID / 4;
    int idx = blockIdx.x * blockDim.x + threadIdx.x;
    if (idx >= TKN * NV) return;
    int t = idx / NV, n4 = idx % NV;
    int s0 = g_slot_of[t * 2 + 0];
    int s1 = g_slot_of[t * 2 + 1];
    float4 o = reinterpret_cast<float4*>(out)[idx];
    const float4* P = reinterpret_cast<const float4*>(g_partial);
    float4 p0 = P[(size_t)s0 * NV + n4];
    float4 p1 = P[(size_t)s1 * NV + n4];
    o.x += p0.x + p1.x;
    o.y += p0.y + p1.y;
    o.z += p0.z + p1.z;
    o.w += p0.w + p1.w;
    reinterpret_cast<float4*>(out)[idx] = o;
}

// ===================== launch =====================
extern "C" void kernel_launch(void* const* d_in, const int* in_sizes, int n_in,
                              void* d_out, int out_size) {
    (void)in_sizes; (void)n_in; (void)out_size;
    const float* x      = (const float*)d_in[0];
    const float* wg     = (const float*)d_in[1];
    const float* wfc    = (const float*)d_in[2];
    const float* wproj  = (const float*)d_in[3];
    const float* wfcs   = (const float*)d_in[4];
    const float* wprojs = (const float*)d_in[5];
    float* out = (float*)d_out;

    static bool attr_set = false;
    if (!attr_set) {
        cudaFuncSetAttribute(mma_gemm<0>, cudaFuncAttributeMaxDynamicSharedMemorySize, SMEM_MMA);
        cudaFuncSetAttribute(mma_gemm<1>, cudaFuncAttributeMaxDynamicSharedMemorySize, SMEM_MMA);
        cudaFuncSetAttribute(mma_gemm<2>, cudaFuncAttributeMaxDynamicSharedMemorySize, SMEM_MMA);
        cudaFuncSetAttribute(mma_gemm<3>, cudaFuncAttributeMaxDynamicSharedMemorySize, SMEM_MMA);
        attr_set = true;
    }

    init_kernel<<<1, 32>>>();
    router_kernel<<<TKN / 8, 256>>>(x, wg);
    prefix_kernel<<<1, 32>>>();
    scatter_kernel<<<TKN / 256, 256>>>();

    {
        __half *hi, *lo, *w;
        cudaGetSymbolAddress((void**)&hi, g_x_hi);  cudaGetSymbolAddress((void**)&lo, g_x_lo);
        split_kernel<<<(TKN * HID) / 1024, 256>>>(x, hi, lo, TKN * HID);
        cudaGetSymbolAddress((void**)&w, g_wfc);
        cvt_kernel<<<(NE * INTR * HID) / 1024, 256>>>(wfc, w, NE * INTR * HID);
        cudaGetSymbolAddress((void**)&w, g_wpj);
        cvt_kernel<<<(NE * HID * INTR) / 1024, 256>>>(wproj, w, NE * HID * INTR);
        cudaGetSymbolAddress((void**)&w, g_wfcs);
        cvt_kernel<<<(SINT * HID) / 1024, 256>>>(wfcs, w, SINT * HID);
        cudaGetSymbolAddress((void**)&w, g_wpjs);
        cvt_kernel<<<(HID * SINT) / 1024, 256>>>(wprojs, w, HID * SINT);
    }

    // expert fc: gathered x -> gelu -> g_h (fp16 hi/lo)
    mma_gemm<0><<<dim3(INTR / 128, TKN * TOPK / 128, NE), 256, SMEM_MMA>>>(nullptr);
    // shared fc: x -> gelu -> g_hs
    mma_gemm<2><<<dim3(SINT / 128, TKN / 128, 1), 256, SMEM_MMA>>>(nullptr);
    // expert proj: g_h -> gate-scaled -> g_partial
    mma_gemm<1><<<dim3(HID / 128, TKN * TOPK / 128, NE), 256, SMEM_MMA>>>(nullptr);
    // shared proj: g_hs -> out
    mma_gemm<3><<<dim3(HID / 128, TKN / 128, 1), 256, SMEM_MMA>>>(out);

    combine_kernel<<<(TKN * (HID / 4)) / 256, 256>>>(out);
}

// round 7
// speedup vs baseline: 6.4786x; 1.6420x over previous
#include <cuda_runtime.h>
#include <cuda_fp16.h>
#include <math.h>
#include <stdint.h>

#define TKN   8192
#define HID   1024
#define NE    8
#define TOPK  2
#define INTR  2048
#define SINT  1024

// ===================== scratch (device globals; no allocations) =====================
__device__ int   g_counts[NE];
__device__ int   g_offsets[NE];
__device__ int   g_cursor[NE];
__device__ __align__(16) int   g_tok[TKN * TOPK];
__device__ __align__(16) float g_gate[TKN * TOPK];
__device__ __align__(16) int   g_slot_of[TKN * TOPK];
__device__ __align__(16) int   g_topidx[TKN * TOPK];
__device__ __align__(16) float g_topgate[TKN * TOPK];

// fp16 operands (single precision-rounded copies)
__device__ __align__(16) __half g_x[(size_t)TKN * HID];
__device__ __align__(16) __half g_h[(size_t)TKN * TOPK * INTR];
__device__ __align__(16) __half g_hs[(size_t)TKN * SINT];
__device__ __align__(16) __half g_wfc[(size_t)NE * INTR * HID];
__device__ __align__(16) __half g_wpj[(size_t)NE * HID * INTR];
__device__ __align__(16) __half g_wfcs[(size_t)SINT * HID];
__device__ __align__(16) __half g_wpjs[(size_t)HID * SINT];
__device__ __align__(16) float g_partial[(size_t)TKN * TOPK * HID];

__device__ __forceinline__ float gelu_exact(float x) {
    return 0.5f * x * (1.0f + erff(x * 0.7071067811865476f));
}

// ===================== PTX helpers (base-target only) =====================
__device__ __forceinline__ uint32_t smem_to_u32(const void* p) {
    uint32_t a;
    asm("{ .reg .u64 t; cvta.to.shared.u64 t, %1; cvt.u32.u64 %0, t; }" : "=r"(a) : "l"(p));
    return a;
}
__device__ __forceinline__ void cp_async16(uint32_t dst, const void* src, uint32_t sz) {
    asm volatile(
        "{ .reg .u64 g; cvta.to.global.u64 g, %1;\n\t"
        "cp.async.cg.shared.global [%0], [g], 16, %2; }"
        :: "r"(dst), "l"(src), "r"(sz));
}
#define CP_COMMIT() asm volatile("cp.async.commit_group;" ::: "memory")
#define CP_WAIT(n)  asm volatile("cp.async.wait_group %0;" :: "n"(n) : "memory")

__device__ __forceinline__ void ldsm4(uint32_t& r0, uint32_t& r1, uint32_t& r2, uint32_t& r3,
                                      uint32_t addr) {
    asm volatile("ldmatrix.sync.aligned.m8n8.x4.shared.b16 {%0,%1,%2,%3}, [%4];"
        : "=r"(r0), "=r"(r1), "=r"(r2), "=r"(r3) : "r"(addr));
}
__device__ __forceinline__ void mma16816(float* c, const uint32_t* a, const uint32_t* b) {
    asm volatile(
        "mma.sync.aligned.m16n8k16.row.col.f32.f16.f16.f32 "
        "{%0,%1,%2,%3}, {%4,%5,%6,%7}, {%8,%9}, {%0,%1,%2,%3};"
        : "+f"(c[0]), "+f"(c[1]), "+f"(c[2]), "+f"(c[3])
        : "r"(a[0]), "r"(a[1]), "r"(a[2]), "r"(a[3]), "r"(b[0]), "r"(b[1]));
}

// swizzled smem layout: rows x 64B (4 chunks of 16B), conflict-free for
// both cp.async stores and ldmatrix reads.
__device__ __forceinline__ uint32_t swz(int r, int c) {
    return (uint32_t)(r * 64 + ((c ^ ((r >> 1) & 3)) << 4));
}

// ===================== small kernels =====================
__global__ void init_kernel() {
    int i = threadIdx.x;
    if (i < NE) g_counts[i] = 0;
}

__global__ void router_kernel(const float* __restrict__ x, const float* __restrict__ wg) {
    __shared__ float s_wg[NE * HID];
    int tid = threadIdx.x;
    for (int i = tid; i < NE * HID; i += blockDim.x) s_wg[i] = wg[i];
    __syncthreads();
    int warp = tid >> 5, lane = tid & 31;
    int t = blockIdx.x * (blockDim.x >> 5) + warp;
    if (t >= TKN) return;
    float acc[NE];
#pragma unroll
    for (int e = 0; e < NE; e++) acc[e] = 0.0f;
    const float* xp = x + (size_t)t * HID;
    for (int k = lane; k < HID; k += 32) {
        float xv = xp[k];
#pragma unroll
        for (int e = 0; e < NE; e++) acc[e] = fmaf(xv, s_wg[e * HID + k], acc[e]);
    }
#pragma unroll
    for (int e = 0; e < NE; e++) {
#pragma unroll
        for (int o = 16; o > 0; o >>= 1) acc[e] += __shfl_xor_sync(0xffffffffu, acc[e], o);
    }
    if (lane == 0) {
        int i0 = 0; float v0 = acc[0];
#pragma unroll
        for (int e = 1; e < NE; e++) { if (acc[e] > v0) { v0 = acc[e]; i0 = e; } }
        int i1 = -1; float v1 = -1e30f;
#pragma unroll
        for (int e = 0; e < NE; e++) { if (e != i0 && acc[e] > v1) { v1 = acc[e]; i1 = e; } }
        float e1 = expf(v1 - v0);
        float denom = 1.0f + e1;
        g_topidx[t * 2 + 0] = i0;  g_topgate[t * 2 + 0] = 1.0f / denom;
        g_topidx[t * 2 + 1] = i1;  g_topgate[t * 2 + 1] = e1 / denom;
        atomicAdd(&g_counts[i0], 1);
        atomicAdd(&g_counts[i1], 1);
    }
}

__global__ void prefix_kernel() {
    if (threadIdx.x == 0) {
        int s = 0;
        for (int e = 0; e < NE; e++) { g_offsets[e] = s; s += g_counts[e]; g_cursor[e] = 0; }
    }
}

__global__ void scatter_kernel() {
    int t = blockIdx.x * blockDim.x + threadIdx.x;
    if (t >= TKN) return;
#pragma unroll
    for (int k = 0; k < TOPK; k++) {
        int e = g_topidx[t * 2 + k];
        int slot = atomicAdd(&g_cursor[e], 1);
        int pos = g_offsets[e] + slot;
        g_tok[pos] = t;
        g_gate[pos] = g_topgate[t * 2 + k];
        g_slot_of[t * 2 + k] = pos;
    }
}

// fp32 -> fp16 (round-to-nearest)
__global__ void cvt_kernel(const float* __restrict__ src, __half* __restrict__ dst, int n) {
    int i = (blockIdx.x * blockDim.x + threadIdx.x) * 4;
    if (i >= n) return;
    float4 v = *reinterpret_cast<const float4*>(src + i);
    uint2 p;
    p.x = (uint32_t)__half_as_ushort(__float2half_rn(v.x)) |
          ((uint32_t)__half_as_ushort(__float2half_rn(v.y)) << 16);
    p.y = (uint32_t)__half_as_ushort(__float2half_rn(v.z)) |
          ((uint32_t)__half_as_ushort(__float2half_rn(v.w)) << 16);
    *reinterpret_cast<uint2*>(dst + i) = p;
}

// ===================== mma.sync grouped GEMM =====================
// Block tile 128x128, BK=32 fp16. 8 warps (2 x 4), warp tile 64x32.
// Single-pass fp16 (A and B both rounded fp16, fp32 accumulate).
// Swizzled 64B-row smem; 4-stage cp.async pipeline; 2 CTAs/SM.
#define TILE_B   8192
#define STAGE_B  16384
#define NSTAGE   4
#define SMEM_MMA (NSTAGE * STAGE_B)

template <int MODE>
__global__ void __launch_bounds__(256, 2) mma_gemm(float* __restrict__ outp)
{
    constexpr int KD = (MODE == 1) ? INTR : HID;
    constexpr int ND = (MODE == 0) ? INTR : ((MODE == 2) ? SINT : HID);
    constexpr int ITERS = KD / 32;

    int rows, base, e = 0;
    if (MODE <= 1) {
        e = blockIdx.z;
        rows = g_counts[e];
        base = g_offsets[e];
    } else { rows = TKN; base = 0; }
    const int bm = blockIdx.y;
    if (bm * 128 >= rows) return;
    const int bn = blockIdx.x;

    extern __shared__ char smem[];
    const uint32_t sb = smem_to_u32(smem);

    const int tid = threadIdx.x;
    const int wid = tid >> 5, lid = tid & 31;
    const int warp_m = wid & 1;
    const int warp_n = wid >> 1;

    const __half *A, *B;
    if (MODE == 0)      A = g_x;
    else if (MODE == 1) A = g_h;
    else if (MODE == 2) A = g_x;
    else                A = g_hs;
    if (MODE == 0)      B = g_wfc  + (size_t)e * INTR * HID;
    else if (MODE == 1) B = g_wpj  + (size_t)e * HID * INTR;
    else if (MODE == 2) B = g_wfcs;
    else                B = g_wpjs;

    float acc[4][4][4];
#pragma unroll
    for (int i = 0; i < 4; i++)
#pragma unroll
        for (int j = 0; j < 4; j++)
#pragma unroll
            for (int q = 0; q < 4; q++) acc[i][j][q] = 0.0f;

    const int lr0 = tid >> 2,         lc0 = tid & 3;
    const int lr1 = (tid + 256) >> 2, lc1 = (tid + 256) & 3;

    auto load_stage = [&](int it) {
        const int s = it & (NSTAGE - 1);
        const int k0 = it * 32;
        const uint32_t stBase = sb + (uint32_t)s * STAGE_B;
#pragma unroll
        for (int l = 0; l < 2; l++) {
            const int r  = l ? lr1 : lr0;
            const int ch = l ? lc1 : lc0;
            const uint32_t so = stBase + swz(r, ch);
            int gm = bm * 128 + r;
            uint32_t szA = 16;
            size_t srow;
            if (MODE == 0) {
                if (gm < rows) srow = (size_t)g_tok[base + gm];
                else { srow = 0; szA = 0; }
            } else if (MODE == 1) {
                if (gm < rows) srow = (size_t)(base + gm);
                else { srow = (size_t)base; szA = 0; }
            } else srow = (size_t)gm;
            size_t goff = srow * KD + k0 + ch * 8;
            cp_async16(so, A + goff, szA);
            size_t boff = (size_t)(bn * 128 + r) * KD + k0 + ch * 8;
            cp_async16(so + TILE_B, B + boff, 16);
        }
    };

    auto compute_stage = [&](int s) {
        const uint32_t aB = sb + (uint32_t)s * STAGE_B;
        const uint32_t bB = aB + TILE_B;
#pragma unroll
        for (int h = 0; h < 2; h++) {
            uint32_t a[4][4], b[4][2];
            const int a_ch = h * 2 + (lid >> 4);
            const int b_ch = h * 2 + ((lid >> 3) & 1);
            const int arow0 = warp_m * 64 + (lid & 7) + ((lid >> 3) & 1) * 8;
#pragma unroll
            for (int jj = 0; jj < 2; jj++) {
                int nrow = warp_n * 32 + jj * 16 + ((lid >> 4) & 1) * 8 + (lid & 7);
                uint32_t bd = bB + swz(nrow, b_ch);
                uint32_t r0, r1, r2, r3;
                ldsm4(r0, r1, r2, r3, bd);
                b[2 * jj][0] = r0; b[2 * jj][1] = r1;
                b[2 * jj + 1][0] = r2; b[2 * jj + 1][1] = r3;
            }
#pragma unroll
            for (int i = 0; i < 4; i++) {
                uint32_t ad = aB + swz(arow0 + i * 16, a_ch);
                ldsm4(a[i][0], a[i][1], a[i][2], a[i][3], ad);
            }
#pragma unroll
            for (int i = 0; i < 4; i++)
#pragma unroll
                for (int j = 0; j < 4; j++) mma16816(acc[i][j], a[i], b[j]);
        }
    };

    // -------- 4-stage pipeline, single sync per iteration --------
    load_stage(0); CP_COMMIT();
    load_stage(1); CP_COMMIT();
    load_stage(2); CP_COMMIT();
#pragma unroll 1
    for (int it = 0; it < ITERS; ++it) {
        CP_WAIT(2);
        __syncthreads();
        if (it + 3 < ITERS) load_stage(it + 3);
        CP_COMMIT();
        compute_stage(it & (NSTAGE - 1));
    }

    // -------- epilogue --------
    const int g = lid >> 2, t4 = lid & 3;
#pragma unroll
    for (int i = 0; i < 4; i++) {
#pragma unroll
        for (int half = 0; half < 2; half++) {
            int row = bm * 128 + warp_m * 64 + i * 16 + g + half * 8;
            if (row >= rows) continue;
            float gate = 1.0f;
            if (MODE == 1) gate = g_gate[base + row];
#pragma unroll
            for (int j = 0; j < 4; j++) {
                float c0 = acc[i][j][half * 2 + 0];
                float c1 = acc[i][j][half * 2 + 1];
                int col = bn * 128 + warp_n * 32 + j * 8 + t4 * 2;
                if (MODE == 0 || MODE == 2) {
                    float f0 = gelu_exact(c0), f1 = gelu_exact(c1);
                    uint32_t hp = (uint32_t)__half_as_ushort(__float2half_rn(f0)) |
                                  ((uint32_t)__half_as_ushort(__float2half_rn(f1)) << 16);
                    __half* H = (MODE == 0) ? g_h : g_hs;
                    size_t off = (MODE == 0) ? ((size_t)(base + row) * ND + col)
                                             : ((size_t)row * ND + col);
                    *reinterpret_cast<uint32_t*>(H + off) = hp;
                } else if (MODE == 1) {
                    size_t off = (size_t)(base + row) * HID + col;
                    float2 v = make_float2(gate * c0, gate * c1);
                    *reinterpret_cast<float2*>(g_partial + off) = v;
                } else {
                    size_t off = (size_t)row * HID + col;
                    float2 v = make_float2(c0, c1);
                    *reinterpret_cast<float2*>(outp + off) = v;
                }
            }
        }
    }
}

// ---------------- combine ----------------
__global__ void combine_kernel(float* __restrict__ out) {
    constexpr int NV = HID / 4;
    int idx = blockIdx.x * blockDim.x + threadIdx.x;
    if (idx >= TKN * NV) return;
    int t = idx / NV, n4 = idx % NV;
    int s0 = g_slot_of[t * 2 + 0];
    int s1 = g_slot_of[t * 2 + 1];
    float4 o = reinterpret_cast<float4*>(out)[idx];
    const float4* P = reinterpret_cast<const float4*>(g_partial);
    float4 p0 = P[(size_t)s0 * NV + n4];
    float4 p1 = P[(size_t)s1 * NV + n4];
    o.x += p0.x + p1.x;
    o.y += p0.y + p1.y;
    o.z += p0.z + p1.z;
    o.w += p0.w + p1.w;
    reinterpret_cast<float4*>(out)[idx] = o;
}

// ===================== launch =====================
extern "C" void kernel_launch(void* const* d_in, const int* in_sizes, int n_in,
                              void* d_out, int out_size) {
    (void)in_sizes; (void)n_in; (void)out_size;
    const float* x      = (const float*)d_in[0];
    const float* wg     = (const float*)d_in[1];
    const float* wfc    = (const float*)d_in[2];
    const float* wproj  = (const float*)d_in[3];
    const float* wfcs   = (const float*)d_in[4];
    const float* wprojs = (const float*)d_in[5];
    float* out = (float*)d_out;

    static bool attr_set = false;
    if (!attr_set) {
        cudaFuncSetAttribute(mma_gemm<0>, cudaFuncAttributeMaxDynamicSharedMemorySize, SMEM_MMA);
        cudaFuncSetAttribute(mma_gemm<1>, cudaFuncAttributeMaxDynamicSharedMemorySize, SMEM_MMA);
        cudaFuncSetAttribute(mma_gemm<2>, cudaFuncAttributeMaxDynamicSharedMemorySize, SMEM_MMA);
        cudaFuncSetAttribute(mma_gemm<3>, cudaFuncAttributeMaxDynamicSharedMemorySize, SMEM_MMA);
        attr_set = true;
    }

    init_kernel<<<1, 32>>>();
    router_kernel<<<TKN / 8, 256>>>(x, wg);
    prefix_kernel<<<1, 32>>>();
    scatter_kernel<<<TKN / 256, 256>>>();

    {
        __half *w;
        cudaGetSymbolAddress((void**)&w, g_x);
        cvt_kernel<<<(TKN * HID) / 1024, 256>>>(x, w, TKN * HID);
        cudaGetSymbolAddress((void**)&w, g_wfc);
        cvt_kernel<<<(NE * INTR * HID) / 1024, 256>>>(wfc, w, NE * INTR * HID);
        cudaGetSymbolAddress((void**)&w, g_wpj);
        cvt_kernel<<<(NE * HID * INTR) / 1024, 256>>>(wproj, w, NE * HID * INTR);
        cudaGetSymbolAddress((void**)&w, g_wfcs);
        cvt_kernel<<<(SINT * HID) / 1024, 256>>>(wfcs, w, SINT * HID);
        cudaGetSymbolAddress((void**)&w, g_wpjs);
        cvt_kernel<<<(HID * SINT) / 1024, 256>>>(wprojs, w, HID * SINT);
    }

    // expert fc: gathered x -> gelu -> g_h (fp16)
    mma_gemm<0><<<dim3(INTR / 128, TKN * TOPK / 128, NE), 256, SMEM_MMA>>>(nullptr);
    // shared fc: x -> gelu -> g_hs
    mma_gemm<2><<<dim3(SINT / 128, TKN / 128, 1), 256, SMEM_MMA>>>(nullptr);
    // expert proj: g_h -> gate-scaled -> g_partial
    mma_gemm<1><<<dim3(HID / 128, TKN * TOPK / 128, NE), 256, SMEM_MMA>>>(nullptr);
    // shared proj: g_hs -> out
    mma_gemm<3><<<dim3(HID / 128, TKN / 128, 1), 256, SMEM_MMA>>>(out);

    combine_kernel<<<(TKN * (HID / 4)) / 256, 256>>>(out);
}